// round 1
// baseline (speedup 1.0000x reference)
#include <cuda_runtime.h>
#include <math.h>

#define B_   64
#define L_   512
#define DQ_  2048
#define H_   128
#define KH_  128
#define DC_  512
#define DCQ_ 1536
#define R_   64
#define SPLITS_ 8

// ---------------- scratch (device globals; no allocation allowed) ----------
__device__ float g_qhk[B_ * H_ * KH_];         // [B][H][K]      4 MB
__device__ float g_Ah[H_ * KH_ * R_];          // [H][K][R]      4 MB
__device__ float g_qr[B_ * H_ * R_];           // [B][H][R]      2 MB
__device__ float g_kv[B_ * L_ * DC_];          // [B][L][DC]    67 MB
__device__ float g_kvsum[B_ * DC_];            // [B][DC]
__device__ float g_scores[B_ * H_ * DC_];      // [B][H][DC]    16 MB (attn in place)
__device__ float g_ctx[B_ * H_ * DC_];         // [B][H][DC]    16 MB
__device__ float g_ctxlat[B_ * H_ * KH_];      // [B][H*K]       4 MB
__device__ float g_part[SPLITS_ * B_ * DQ_];   // split-K partials 4 MB

// ---------------- generic tiled fp32 GEMM --------------------------------
// C[m,n] = sum_k A[m,k] * B(n,k or k,n)    (BT=true: B is [N,K] row-major (NT))
// batched over blockIdx.z with element strides sAz/sBz/sCz.
template <int BM, int BN, int BK, int TM, int TN, bool BT>
__global__ __launch_bounds__((BM / TM) * (BN / TN))
void gemm_tpl(const float* __restrict__ A, const float* __restrict__ B,
              float* __restrict__ C, int M, int N, int Kd,
              long sAz, long sBz, long sCz, int lda, int ldb, int ldc) {
    constexpr int THREADS = (BM / TM) * (BN / TN);
    __shared__ __align__(16) float As[BK][BM + 4];
    __shared__ __align__(16) float Bs[BK][BN + 4];

    const float* Ab = A + (long)blockIdx.z * sAz + (long)blockIdx.y * BM * lda;
    const int n0 = blockIdx.x * BN;
    const float* Bb = BT ? (B + (long)blockIdx.z * sBz + (long)n0 * ldb)
                         : (B + (long)blockIdx.z * sBz + n0);
    float* Cb = C + (long)blockIdx.z * sCz;

    const int tid = threadIdx.x;
    const int tcol = tid % (BN / TN);
    const int trow = tid / (BN / TN);

    float acc[TM][TN];
#pragma unroll
    for (int i = 0; i < TM; i++)
#pragma unroll
        for (int j = 0; j < TN; j++) acc[i][j] = 0.f;

    for (int k0 = 0; k0 < Kd; k0 += BK) {
#pragma unroll
        for (int i = 0; i < (BM * BK) / THREADS; i++) {
            int idx = tid + i * THREADS;
            int am = idx / BK, ak = idx % BK;
            As[ak][am] = Ab[(long)am * lda + k0 + ak];
        }
#pragma unroll
        for (int i = 0; i < (BN * BK) / THREADS; i++) {
            int idx = tid + i * THREADS;
            if (BT) {
                int bn = idx / BK, bk = idx % BK;
                Bs[bk][bn] = Bb[(long)bn * ldb + k0 + bk];
            } else {
                int bk = idx / BN, bn = idx % BN;
                Bs[bk][bn] = Bb[(long)(k0 + bk) * ldb + bn];
            }
        }
        __syncthreads();
#pragma unroll
        for (int kk = 0; kk < BK; kk++) {
            float a[TM], bv[TN];
#pragma unroll
            for (int i = 0; i < TM; i += 4) {
                float4 t = *(const float4*)&As[kk][trow * TM + i];
                a[i] = t.x; a[i + 1] = t.y; a[i + 2] = t.z; a[i + 3] = t.w;
            }
#pragma unroll
            for (int j = 0; j < TN; j += 4) {
                float4 t = *(const float4*)&Bs[kk][tcol * TN + j];
                bv[j] = t.x; bv[j + 1] = t.y; bv[j + 2] = t.z; bv[j + 3] = t.w;
            }
#pragma unroll
            for (int i = 0; i < TM; i++)
#pragma unroll
                for (int j = 0; j < TN; j++) acc[i][j] += a[i] * bv[j];
        }
        __syncthreads();
    }

#pragma unroll
    for (int i = 0; i < TM; i++) {
        int m = blockIdx.y * BM + trow * TM + i;
#pragma unroll
        for (int j = 0; j < TN; j++)
            Cb[(long)m * ldc + n0 + tcol * TN + j] = acc[i][j];
    }
}

// ---------------- RoPE:  kv = kv_c*cos + rotate_half(kv_c)*sin ------------
__global__ __launch_bounds__(DC_) void rope_kernel(const float* __restrict__ kv_c) {
    const int l = blockIdx.x;
    const int b = blockIdx.y;
    const int d = threadIdx.x;
    const long base = ((long)b * L_ + l) * DC_;
    float x = kv_c[base + d];
    float xr = (d < DC_ / 2) ? -kv_c[base + d + DC_ / 2] : kv_c[base + d - DC_ / 2];
    float ex = (float)(d & ~1) * (1.0f / (float)DC_);
    float inv = exp2f(-13.287712379549449f * ex);  // 10000^{-ex}
    float ang = (float)l * inv;
    float s, c;
    sincosf(ang, &s, &c);
    g_kv[base + d] = x * c + xr * s;
}

// ---------------- kvsum[b,d] = sum_l kv[b,l,d] ----------------------------
__global__ __launch_bounds__(128) void kvsum_kernel() {
    const int b = blockIdx.x;
    const int d = blockIdx.y * 128 + threadIdx.x;
    const float* p = g_kv + (long)b * L_ * DC_ + d;
    float s = 0.f;
#pragma unroll 8
    for (int l = 0; l < L_; l++) s += p[(long)l * DC_];
    g_kvsum[b * DC_ + d] = s;
}

// ---------------- scores[b,h,d] = kvsum[b,d] * sum_r qr[b,h,r]*Wkr[h,d,r] -
__global__ __launch_bounds__(256) void scores_kernel(const float* __restrict__ Wkr) {
    const int h = blockIdx.x;
    __shared__ __align__(16) float qs[B_][R_ + 4];   // [b][r]
    __shared__ __align__(16) float ws[64][R_ + 4];   // [dd][r]
    const int tid = threadIdx.x;
    const int tcol = tid % 16;  // dd group (x4)
    const int trow = tid / 16;  // b  group (x4)

#pragma unroll
    for (int i = 0; i < 16; i++) {
        int idx = tid + i * 256;
        int b = idx >> 6, r = idx & 63;
        qs[b][r] = g_qr[((long)b * H_ + h) * R_ + r];
    }

    for (int d0 = 0; d0 < DC_; d0 += 64) {
        __syncthreads();
#pragma unroll
        for (int i = 0; i < 16; i++) {
            int idx = tid + i * 256;
            int dd = idx >> 6, r = idx & 63;
            ws[dd][r] = Wkr[((long)h * DC_ + d0 + dd) * R_ + r];
        }
        __syncthreads();
        float acc[4][4];
#pragma unroll
        for (int i = 0; i < 4; i++)
#pragma unroll
            for (int j = 0; j < 4; j++) acc[i][j] = 0.f;
#pragma unroll 8
        for (int r = 0; r < R_; r++) {
            float a[4], bv[4];
#pragma unroll
            for (int i = 0; i < 4; i++) a[i] = qs[trow * 4 + i][r];
#pragma unroll
            for (int j = 0; j < 4; j++) bv[j] = ws[tcol * 4 + j][r];
#pragma unroll
            for (int i = 0; i < 4; i++)
#pragma unroll
                for (int j = 0; j < 4; j++) acc[i][j] += a[i] * bv[j];
        }
#pragma unroll
        for (int i = 0; i < 4; i++) {
            int b = trow * 4 + i;
#pragma unroll
            for (int j = 0; j < 4; j++) {
                int d = d0 + tcol * 4 + j;
                g_scores[((long)b * H_ + h) * DC_ + d] = acc[i][j] * g_kvsum[b * DC_ + d];
            }
        }
    }
}

// ---------------- softmax over d (in place on g_scores) -------------------
__global__ __launch_bounds__(128) void softmax_kernel() {
    const int bh = blockIdx.x;
    float* p = g_scores + (long)bh * DC_;
    const int tid = threadIdx.x;
    __shared__ float red[128];
    float v[4];
    float mx = -1e30f;
#pragma unroll
    for (int i = 0; i < 4; i++) {
        v[i] = p[tid + i * 128];
        mx = fmaxf(mx, v[i]);
    }
    red[tid] = mx;
    __syncthreads();
    for (int s = 64; s > 0; s >>= 1) {
        if (tid < s) red[tid] = fmaxf(red[tid], red[tid + s]);
        __syncthreads();
    }
    mx = red[0];
    __syncthreads();
    float sum = 0.f;
#pragma unroll
    for (int i = 0; i < 4; i++) {
        v[i] = expf(v[i] - mx);
        sum += v[i];
    }
    red[tid] = sum;
    __syncthreads();
    for (int s = 64; s > 0; s >>= 1) {
        if (tid < s) red[tid] += red[tid + s];
        __syncthreads();
    }
    float invs = 1.0f / red[0];
#pragma unroll
    for (int i = 0; i < 4; i++) p[tid + i * 128] = v[i] * invs;
}

// ---------------- split-K reduce into d_out -------------------------------
__global__ __launch_bounds__(256) void reduce_kernel(float* __restrict__ out) {
    const int i = blockIdx.x * 256 + threadIdx.x;  // grid sized exactly
    float s = 0.f;
#pragma unroll
    for (int z = 0; z < SPLITS_; z++) s += g_part[(long)z * B_ * DQ_ + i];
    out[i] = s;
}

// ---------------- launch --------------------------------------------------
extern "C" void kernel_launch(void* const* d_in, const int* in_sizes, int n_in,
                              void* d_out, int out_size) {
    const float* hidden_q  = (const float*)d_in[0];
    const float* kv_c      = (const float*)d_in[1];
    const float* q_proj_w  = (const float*)d_in[2];
    const float* w_kc_q    = (const float*)d_in[3];
    const float* w_kc_kv   = (const float*)d_in[4];
    const float* W_qr      = (const float*)d_in[5];
    const float* W_kr      = (const float*)d_in[6];
    const float* out_proj_w = (const float*)d_in[7];
    float* out = (float*)d_out;

    float *qhk, *Ah, *qr, *kv, *scores, *ctx, *ctxlat, *part;
    cudaGetSymbolAddress((void**)&qhk,    g_qhk);
    cudaGetSymbolAddress((void**)&Ah,     g_Ah);
    cudaGetSymbolAddress((void**)&qr,     g_qr);
    cudaGetSymbolAddress((void**)&kv,     g_kv);
    cudaGetSymbolAddress((void**)&scores, g_scores);
    cudaGetSymbolAddress((void**)&ctx,    g_ctx);
    cudaGetSymbolAddress((void**)&ctxlat, g_ctxlat);
    cudaGetSymbolAddress((void**)&part,   g_part);

    // RoPE + kvsum (independent of q path)
    rope_kernel<<<dim3(L_, B_), DC_>>>(kv_c);
    kvsum_kernel<<<dim3(B_, 4), 128>>>();

    // q_hk[b, h*K+k] = hidden_q[b,:] . q_proj_w[h*K+k,:]   (NT)
    gemm_tpl<64, 128, 16, 8, 4, true><<<dim3(DQ_ * 8 / 128, 1, 1), 256>>>(
        hidden_q, q_proj_w, qhk, B_, H_ * KH_, DQ_, 0, 0, 0, DQ_, DQ_, H_ * KH_);

    // A_h[k,r] = sum_q w_kc_q[h,k,q] * W_qr[h,q,r]   (NN, batched over h)
    gemm_tpl<64, 64, 16, 4, 4, false><<<dim3(1, 2, H_), 256>>>(
        w_kc_q, W_qr, Ah, KH_, R_, DCQ_,
        (long)KH_ * DCQ_, (long)DCQ_ * R_, (long)KH_ * R_, DCQ_, R_, R_);

    // q_r[b,h,r] = sum_k q_hk[b,h,k] * A_h[k,r]      (NN, batched over h)
    gemm_tpl<64, 64, 16, 4, 4, false><<<dim3(1, 1, H_), 256>>>(
        qhk, Ah, qr, B_, R_, KH_,
        (long)KH_, (long)KH_ * R_, (long)R_, H_ * KH_, R_, H_ * R_);

    // scores + softmax
    scores_kernel<<<H_, 256>>>(W_kr);
    softmax_kernel<<<B_ * H_, 128>>>();

    // ctx[b,h,d] = sum_j attn[b,h,j] * kv[b,j,d]     (NN, batched over b)
    gemm_tpl<64, 128, 16, 8, 4, false><<<dim3(DC_ / 128, H_ / 64, B_), 256>>>(
        scores, kv, ctx, H_, DC_, DC_,
        (long)H_ * DC_, (long)L_ * DC_, (long)H_ * DC_, DC_, DC_, DC_);

    // ctxlat[b, h*K+k] = sum_d ctx[b,h,d] * w_kc_kv[h,k,d]  (NT, batched over h)
    gemm_tpl<64, 128, 16, 8, 4, true><<<dim3(1, 1, H_), 256>>>(
        ctx, w_kc_kv, ctxlat, B_, KH_, DC_,
        (long)DC_, (long)KH_ * DC_, (long)KH_, H_ * DC_, DC_, H_ * KH_);

    // out[b,dq] = sum_n ctxlat[b,n] * out_proj_w[dq,n]  (NT, split-K x8)
    gemm_tpl<64, 128, 16, 8, 4, true><<<dim3(DQ_ / 128, 1, SPLITS_), 256>>>(
        ctxlat, out_proj_w, part, B_, DQ_, H_ * KH_ / SPLITS_,
        (long)(H_ * KH_ / SPLITS_), (long)(H_ * KH_ / SPLITS_), (long)B_ * DQ_,
        H_ * KH_, H_ * KH_, DQ_);
    reduce_kernel<<<B_ * DQ_ / 256, 256>>>(out);
}

// round 3
// speedup vs baseline: 1.1242x; 1.1242x over previous
#include <cuda_runtime.h>
#include <math.h>
#include <stdint.h>

#define B_   64
#define L_   512
#define DQ_  2048
#define H_   128
#define KH_  128
#define DC_  512
#define DCQ_ 1536
#define R_   64
#define SPLITS_ 16

// ---------------- scratch (device globals; no allocation allowed) ----------
__device__ float g_qhk[B_ * H_ * KH_];
__device__ float g_Ah[H_ * KH_ * R_];
__device__ float g_qr[B_ * H_ * R_];
__device__ float g_kv[B_ * L_ * DC_];
__device__ float g_kvsum[B_ * DC_];
__device__ float g_scores[B_ * H_ * DC_];
__device__ float g_ctx[B_ * H_ * DC_];
__device__ float g_ctxlat[B_ * H_ * KH_];
__device__ float g_part[SPLITS_ * B_ * DQ_];

// ---------------- helpers --------------------------------------------------
__device__ __forceinline__ float to_tf32(float x) {
    float y; asm("cvt.rna.tf32.f32 %0, %1;" : "=f"(y) : "f"(x)); return y;
}

#define MMA8(d, a, b)                                                         \
    asm volatile(                                                             \
        "mma.sync.aligned.m16n8k8.row.col.f32.tf32.tf32.f32 "                 \
        "{%0,%1,%2,%3}, {%4,%5,%6,%7}, {%8,%9}, {%0,%1,%2,%3};"               \
        : "+f"((d)[0]), "+f"((d)[1]), "+f"((d)[2]), "+f"((d)[3])              \
        : "r"((a)[0]), "r"((a)[1]), "r"((a)[2]), "r"((a)[3]),                 \
          "r"((b)[0]), "r"((b)[1]))

// ---------------- tf32 mma.sync GEMM  (BM=64, BN=64, BK=32, 128 thr) -------
// C[m,n] = sum_k A[m,k] * B[n,k].  TRANSB: B source is [K,N] row-major.
// SPLIT: 3xTF32 hi/lo error-compensated path. BIAS: C += bias[n]*bscale.
// SMEM fragment-major layout:
//   A: [kstep(4)][mtile(4)][lane(32)][elem(4)]  (elem = grp + 2*chalf)
//   B: [kstep(4)][ntile(8)][lane(32)][elem(2)]  (elem = khalf)
template <bool TRANSB, bool SPLIT, bool BIAS>
__global__ __launch_bounds__(128)
void mgemm(const float* __restrict__ A, const float* __restrict__ Bm,
           float* __restrict__ C, const float* __restrict__ bias,
           float bscale, long sBiasz, int Kd,
           long sAz, long sBz, long sCz, int lda, int ldb, int ldc) {
    __shared__ uint32_t AsH[2048], BsH[2048];
    __shared__ uint32_t AsL[SPLIT ? 2048 : 4], BsL[SPLIT ? 2048 : 4];

    const int tid = threadIdx.x, lane = tid & 31, wid = tid >> 5;
    const int wm = wid >> 1, wn = wid & 1;
    const int n0 = blockIdx.x * 64, m0 = blockIdx.y * 64, bz = blockIdx.z;

    const float* Ab = A + (long)bz * sAz + (long)m0 * lda;
    const float* Bb = TRANSB ? (Bm + (long)bz * sBz + n0)
                             : (Bm + (long)bz * sBz + (long)n0 * ldb);
    float* Cb = C + (long)bz * sCz;

    float acc[2][4][4];
#pragma unroll
    for (int mi = 0; mi < 2; mi++)
#pragma unroll
        for (int nj = 0; nj < 4; nj++)
#pragma unroll
            for (int e = 0; e < 4; e++) acc[mi][nj][e] = 0.f;

    const int nch = Kd >> 5;
    for (int ch = 0; ch < nch; ch++) {
        const int k0 = ch << 5;
        // ---- stage A (64 rows x 32 k) into fragment-major SMEM ----
#pragma unroll
        for (int i = 0; i < 4; i++) {
            int idx = tid + (i << 7);
            int row = idx >> 3, c4 = idx & 7;
            float4 v = *(const float4*)(Ab + (long)row * lda + k0 + (c4 << 2));
            int kstep = c4 >> 1, chalf = c4 & 1;
            int base = (((kstep << 2) + (row >> 4)) << 5) + ((row & 7) << 2);
            int elem = ((row >> 3) & 1) + (chalf << 1);
            float vv[4] = {v.x, v.y, v.z, v.w};
#pragma unroll
            for (int j = 0; j < 4; j++) {
                float h = to_tf32(vv[j]);
                AsH[((base + j) << 2) + elem] = __float_as_uint(h);
                if (SPLIT)
                    AsL[((base + j) << 2) + elem] =
                        __float_as_uint(to_tf32(vv[j] - h));
            }
        }
        // ---- stage B (64 n x 32 k) ----
        if (!TRANSB) {
#pragma unroll
            for (int i = 0; i < 4; i++) {
                int idx = tid + (i << 7);
                int n = idx >> 3, c4 = idx & 7;
                float4 v = *(const float4*)(Bb + (long)n * ldb + k0 + (c4 << 2));
                int kstep = c4 >> 1, khalf = c4 & 1;
                int base = (((kstep << 3) + (n >> 3)) << 5) + ((n & 7) << 2);
                float vv[4] = {v.x, v.y, v.z, v.w};
#pragma unroll
                for (int j = 0; j < 4; j++) {
                    float h = to_tf32(vv[j]);
                    BsH[((base + j) << 1) + khalf] = __float_as_uint(h);
                    if (SPLIT)
                        BsL[((base + j) << 1) + khalf] =
                            __float_as_uint(to_tf32(vv[j] - h));
                }
            }
        } else {
#pragma unroll
            for (int i = 0; i < 4; i++) {
                int idx = tid + (i << 7);
                int k = idx >> 4, n4 = idx & 15;
                float4 v = *(const float4*)(Bb + (long)(k0 + k) * ldb + (n4 << 2));
                int kstep = k >> 3, khalf = (k >> 2) & 1, kc = k & 3;
                float vv[4] = {v.x, v.y, v.z, v.w};
#pragma unroll
                for (int j = 0; j < 4; j++) {
                    int n = (n4 << 2) + j;
                    int di = (((((kstep << 3) + (n >> 3)) << 5) +
                               ((n & 7) << 2) + kc) << 1) + khalf;
                    float h = to_tf32(vv[j]);
                    BsH[di] = __float_as_uint(h);
                    if (SPLIT) BsL[di] = __float_as_uint(to_tf32(vv[j] - h));
                }
            }
        }
        __syncthreads();
        // ---- compute: 4 k-steps of m16n8k8 ----
#pragma unroll
        for (int ks = 0; ks < 4; ks++) {
            uint32_t af[2][4], bf[4][2];
#pragma unroll
            for (int mi = 0; mi < 2; mi++) {
                uint4 t = *(const uint4*)
                    &AsH[((((ks << 2) + (wm << 1) + mi) << 5) + lane) << 2];
                af[mi][0] = t.x; af[mi][1] = t.y; af[mi][2] = t.z; af[mi][3] = t.w;
            }
#pragma unroll
            for (int nj = 0; nj < 4; nj++) {
                uint2 t = *(const uint2*)
                    &BsH[((((ks << 3) + (wn << 2) + nj) << 5) + lane) << 1];
                bf[nj][0] = t.x; bf[nj][1] = t.y;
            }
#pragma unroll
            for (int mi = 0; mi < 2; mi++)
#pragma unroll
                for (int nj = 0; nj < 4; nj++) MMA8(acc[mi][nj], af[mi], bf[nj]);
            if (SPLIT) {
                uint32_t al[2][4], bl[4][2];
#pragma unroll
                for (int mi = 0; mi < 2; mi++) {
                    uint4 t = *(const uint4*)
                        &AsL[((((ks << 2) + (wm << 1) + mi) << 5) + lane) << 2];
                    al[mi][0] = t.x; al[mi][1] = t.y; al[mi][2] = t.z; al[mi][3] = t.w;
                }
#pragma unroll
                for (int nj = 0; nj < 4; nj++) {
                    uint2 t = *(const uint2*)
                        &BsL[((((ks << 3) + (wn << 2) + nj) << 5) + lane) << 1];
                    bl[nj][0] = t.x; bl[nj][1] = t.y;
                }
#pragma unroll
                for (int mi = 0; mi < 2; mi++)
#pragma unroll
                    for (int nj = 0; nj < 4; nj++) {
                        MMA8(acc[mi][nj], af[mi], bl[nj]);
                        MMA8(acc[mi][nj], al[mi], bf[nj]);
                    }
            }
        }
        __syncthreads();
    }

    // ---- epilogue: direct fragment stores ----
    const float* bias_b = BIAS ? (bias + (long)bz * sBiasz) : (const float*)0;
#pragma unroll
    for (int mi = 0; mi < 2; mi++)
#pragma unroll
        for (int nj = 0; nj < 4; nj++) {
            int r = m0 + wm * 32 + mi * 16 + (lane >> 2);
            int c = n0 + wn * 32 + nj * 8 + ((lane & 3) << 1);
            float2 v0 = make_float2(acc[mi][nj][0], acc[mi][nj][1]);
            float2 v1 = make_float2(acc[mi][nj][2], acc[mi][nj][3]);
            if (BIAS) {
                float b0 = bias_b[c] * bscale, b1 = bias_b[c + 1] * bscale;
                v0.x += b0; v0.y += b1; v1.x += b0; v1.y += b1;
            }
            *(float2*)&Cb[(long)r * ldc + c] = v0;
            *(float2*)&Cb[(long)(r + 8) * ldc + c] = v1;
        }
}

// ---------------- RoPE ----------------------------------------------------
__global__ __launch_bounds__(DC_) void rope_kernel(const float* __restrict__ kv_c) {
    const int l = blockIdx.x;
    const int b = blockIdx.y;
    const int d = threadIdx.x;
    const long base = ((long)b * L_ + l) * DC_;
    float x = kv_c[base + d];
    float xr = (d < DC_ / 2) ? -kv_c[base + d + DC_ / 2] : kv_c[base + d - DC_ / 2];
    float ex = (float)(d & ~1) * (1.0f / (float)DC_);
    float inv = exp2f(-13.287712379549449f * ex);  // 10000^{-ex}
    float ang = (float)l * inv;
    float s, c;
    sincosf(ang, &s, &c);
    g_kv[base + d] = x * c + xr * s;
}

// ---------------- kvsum[b,d] = sum_l kv[b,l,d] ----------------------------
__global__ __launch_bounds__(128) void kvsum_kernel() {
    const int b = blockIdx.x;
    const int d = blockIdx.y * 128 + threadIdx.x;
    const float* p = g_kv + (long)b * L_ * DC_ + d;
    float s = 0.f;
#pragma unroll 8
    for (int l = 0; l < L_; l++) s += p[(long)l * DC_];
    g_kvsum[b * DC_ + d] = s;
}

// ---------------- scores[b,h,d] = kvsum[b,d] * sum_r qr[b,h,r]*Wkr[h,d,r] -
__global__ __launch_bounds__(256) void scores_kernel(const float* __restrict__ Wkr) {
    const int h = blockIdx.x;
    __shared__ __align__(16) float qs[B_][R_ + 4];
    __shared__ __align__(16) float ws[64][R_ + 4];
    const int tid = threadIdx.x;
    const int tcol = tid % 16;
    const int trow = tid / 16;

#pragma unroll
    for (int i = 0; i < 16; i++) {
        int idx = tid + i * 256;
        int b = idx >> 6, r = idx & 63;
        qs[b][r] = g_qr[((long)b * H_ + h) * R_ + r];
    }

    for (int d0 = 0; d0 < DC_; d0 += 64) {
        __syncthreads();
#pragma unroll
        for (int i = 0; i < 16; i++) {
            int idx = tid + i * 256;
            int dd = idx >> 6, r = idx & 63;
            ws[dd][r] = Wkr[((long)h * DC_ + d0 + dd) * R_ + r];
        }
        __syncthreads();
        float acc[4][4];
#pragma unroll
        for (int i = 0; i < 4; i++)
#pragma unroll
            for (int j = 0; j < 4; j++) acc[i][j] = 0.f;
#pragma unroll 8
        for (int r = 0; r < R_; r++) {
            float a[4], bv[4];
#pragma unroll
            for (int i = 0; i < 4; i++) a[i] = qs[trow * 4 + i][r];
#pragma unroll
            for (int j = 0; j < 4; j++) bv[j] = ws[tcol * 4 + j][r];
#pragma unroll
            for (int i = 0; i < 4; i++)
#pragma unroll
                for (int j = 0; j < 4; j++) acc[i][j] += a[i] * bv[j];
        }
#pragma unroll
        for (int i = 0; i < 4; i++) {
            int b = trow * 4 + i;
#pragma unroll
            for (int j = 0; j < 4; j++) {
                int d = d0 + tcol * 4 + j;
                g_scores[((long)b * H_ + h) * DC_ + d] = acc[i][j] * g_kvsum[b * DC_ + d];
            }
        }
    }
}

// ---------------- softmax, then subtract uniform mode 1/512 ---------------
__global__ __launch_bounds__(128) void softmax_kernel() {
    const int bh = blockIdx.x;
    float* p = g_scores + (long)bh * DC_;
    const int tid = threadIdx.x;
    __shared__ float red[128];
    float v[4];
    float mx = -1e30f;
#pragma unroll
    for (int i = 0; i < 4; i++) {
        v[i] = p[tid + i * 128];
        mx = fmaxf(mx, v[i]);
    }
    red[tid] = mx;
    __syncthreads();
    for (int s = 64; s > 0; s >>= 1) {
        if (tid < s) red[tid] = fmaxf(red[tid], red[tid + s]);
        __syncthreads();
    }
    mx = red[0];
    __syncthreads();
    float sum = 0.f;
#pragma unroll
    for (int i = 0; i < 4; i++) {
        v[i] = expf(v[i] - mx);
        sum += v[i];
    }
    red[tid] = sum;
    __syncthreads();
    for (int s = 64; s > 0; s >>= 1) {
        if (tid < s) red[tid] += red[tid + s];
        __syncthreads();
    }
    float invs = 1.0f / red[0];
#pragma unroll
    for (int i = 0; i < 4; i++)
        p[tid + i * 128] = v[i] * invs - (1.0f / 512.0f);
}

// ---------------- split-K reduce into d_out -------------------------------
__global__ __launch_bounds__(256) void reduce_kernel(float* __restrict__ out) {
    const int i = blockIdx.x * 256 + threadIdx.x;
    float s = 0.f;
#pragma unroll
    for (int z = 0; z < SPLITS_; z++) s += g_part[(long)z * B_ * DQ_ + i];
    out[i] = s;
}

// ---------------- launch --------------------------------------------------
extern "C" void kernel_launch(void* const* d_in, const int* in_sizes, int n_in,
                              void* d_out, int out_size) {
    const float* hidden_q   = (const float*)d_in[0];
    const float* kv_c       = (const float*)d_in[1];
    const float* q_proj_w   = (const float*)d_in[2];
    const float* w_kc_q     = (const float*)d_in[3];
    const float* w_kc_kv    = (const float*)d_in[4];
    const float* W_qr       = (const float*)d_in[5];
    const float* W_kr       = (const float*)d_in[6];
    const float* out_proj_w = (const float*)d_in[7];
    float* out = (float*)d_out;

    float *qhk, *Ah, *qr, *kvsum, *scores, *ctx, *ctxlat, *part, *kv;
    cudaGetSymbolAddress((void**)&qhk,    g_qhk);
    cudaGetSymbolAddress((void**)&Ah,     g_Ah);
    cudaGetSymbolAddress((void**)&qr,     g_qr);
    cudaGetSymbolAddress((void**)&kv,     g_kv);
    cudaGetSymbolAddress((void**)&kvsum,  g_kvsum);
    cudaGetSymbolAddress((void**)&scores, g_scores);
    cudaGetSymbolAddress((void**)&ctx,    g_ctx);
    cudaGetSymbolAddress((void**)&ctxlat, g_ctxlat);
    cudaGetSymbolAddress((void**)&part,   g_part);

    rope_kernel<<<dim3(L_, B_), DC_>>>(kv_c);
    kvsum_kernel<<<dim3(B_, 4), 128>>>();

    // q_hk = hidden_q @ q_proj_w^T   [64 x 16384], K=2048
    mgemm<false, false, false><<<dim3(256, 1, 1), 128>>>(
        hidden_q, q_proj_w, qhk, (const float*)0, 0.f, 0,
        DQ_, 0, 0, 0, DQ_, DQ_, H_ * KH_);

    // A_h = w_kc_q[h] @ W_qr[h]   (B source [q,r] -> trans)  [128 x 64] x128
    mgemm<true, false, false><<<dim3(1, 2, H_), 128>>>(
        w_kc_q, W_qr, Ah, (const float*)0, 0.f, 0,
        DCQ_, (long)KH_ * DCQ_, (long)DCQ_ * R_, (long)KH_ * R_,
        DCQ_, R_, R_);

    // q_r = q_hk[:,h,:] @ A_h   (B source [k,r] -> trans)  [64 x 64] x128
    mgemm<true, false, false><<<dim3(1, 1, H_), 128>>>(
        qhk, Ah, qr, (const float*)0, 0.f, 0,
        KH_, (long)KH_, (long)KH_ * R_, (long)R_, H_ * KH_, R_, H_ * R_);

    scores_kernel<<<H_, 256>>>(W_kr);
    softmax_kernel<<<B_ * H_, 128>>>();

    // ctx = (attn - 1/512) @ kv + kvsum/512  (B source [j,d] -> trans, bias)
    mgemm<true, false, true><<<dim3(DC_ / 64, 2, B_), 128>>>(
        scores, kv, ctx, kvsum, 1.0f / 512.0f, (long)DC_,
        DC_, (long)H_ * DC_, (long)L_ * DC_, (long)H_ * DC_,
        DC_, DC_, DC_);

    // ctxlat = ctx[:,h,:] @ w_kc_kv[h]^T   (3xTF32 split)  [64 x 128] x128
    mgemm<false, true, false><<<dim3(KH_ / 64, 1, H_), 128>>>(
        ctx, w_kc_kv, ctxlat, (const float*)0, 0.f, 0,
        DC_, (long)DC_, (long)KH_ * DC_, (long)KH_, H_ * DC_, DC_, H_ * KH_);

    // out = ctxlat @ out_proj_w^T  (3xTF32 split, split-K x16)
    mgemm<false, true, false><<<dim3(DQ_ / 64, 1, SPLITS_), 128>>>(
        ctxlat, out_proj_w, part, (const float*)0, 0.f, 0,
        H_ * KH_ / SPLITS_,
        (long)(H_ * KH_ / SPLITS_), (long)(H_ * KH_ / SPLITS_), (long)B_ * DQ_,
        H_ * KH_, H_ * KH_, DQ_);
    reduce_kernel<<<B_ * DQ_ / 256, 256>>>(out);
}

// round 4
// speedup vs baseline: 1.1659x; 1.0371x over previous
#include <cuda_runtime.h>
#include <math.h>
#include <stdint.h>

#define B_   64
#define L_   512
#define DQ_  2048
#define H_   128
#define KH_  128
#define DC_  512
#define DCQ_ 1536
#define R_   64
#define SPLITS_ 16

// ---------------- scratch (device globals; no allocation allowed) ----------
__device__ float g_qhk[B_ * H_ * KH_];
__device__ float g_Ah[H_ * KH_ * R_];
__device__ float g_qr[B_ * H_ * R_];
__device__ float g_kv[B_ * L_ * DC_];
__device__ float g_kvsum[B_ * DC_];
__device__ float g_scores[B_ * H_ * DC_];
__device__ float g_ctx[B_ * H_ * DC_];
__device__ float g_ctxlat[B_ * H_ * KH_];
__device__ float g_part[SPLITS_ * B_ * DQ_];

// ---------------- helpers --------------------------------------------------
__device__ __forceinline__ float to_tf32(float x) {
    float y; asm("cvt.rna.tf32.f32 %0, %1;" : "=f"(y) : "f"(x)); return y;
}

#define MMA8(d, a, b)                                                         \
    asm volatile(                                                             \
        "mma.sync.aligned.m16n8k8.row.col.f32.tf32.tf32.f32 "                 \
        "{%0,%1,%2,%3}, {%4,%5,%6,%7}, {%8,%9}, {%0,%1,%2,%3};"               \
        : "+f"((d)[0]), "+f"((d)[1]), "+f"((d)[2]), "+f"((d)[3])              \
        : "r"((a)[0]), "r"((a)[1]), "r"((a)[2]), "r"((a)[3]),                 \
          "r"((b)[0]), "r"((b)[1]))

// ---------------- tf32 mma.sync GEMM  (BM=64, BN=64, BK=32, 256 thr) -------
// C[m,n] = sum_k A[m,k] * B[n,k].  TRANSB: B source is [K,N] row-major.
// SPLIT: 3xTF32 hi/lo error-compensated path. BIAS: C += bias[n]*bscale.
// 8 warps: wm(2) x wn(4); warp tile 32x16 (frags 2m x 2n of m16n8).
// Register-prefetch pipeline: LDG chunk ch+1 overlaps HMMA of chunk ch.
// SMEM fragment-major layout:
//   A: [kstep(4)][mtile(4)][lane(32)][elem(4)]  (elem = grp + 2*chalf)
//   B: [kstep(4)][ntile(8)][lane(32)][elem(2)]  (elem = khalf)
template <bool TRANSB, bool SPLIT, bool BIAS>
__global__ __launch_bounds__(256)
void mgemm(const float* __restrict__ A, const float* __restrict__ Bm,
           float* __restrict__ C, const float* __restrict__ bias,
           float bscale, long sBiasz, int Kd,
           long sAz, long sBz, long sCz, int lda, int ldb, int ldc) {
    __shared__ uint32_t AsH[2048], BsH[2048];
    __shared__ uint32_t AsL[SPLIT ? 2048 : 4], BsL[SPLIT ? 2048 : 4];

    const int tid = threadIdx.x, lane = tid & 31, wid = tid >> 5;
    const int wm = wid >> 2, wn = wid & 3;
    const int n0 = blockIdx.x * 64, m0 = blockIdx.y * 64, bz = blockIdx.z;

    const float* Ab = A + (long)bz * sAz + (long)m0 * lda;
    const float* Bb = TRANSB ? (Bm + (long)bz * sBz + n0)
                             : (Bm + (long)bz * sBz + (long)n0 * ldb);
    float* Cb = C + (long)bz * sCz;

    float acc[2][2][4];
#pragma unroll
    for (int mi = 0; mi < 2; mi++)
#pragma unroll
        for (int nj = 0; nj < 2; nj++)
#pragma unroll
            for (int e = 0; e < 4; e++) acc[mi][nj][e] = 0.f;

    // per-thread staging coords
    const int a_row0 = tid >> 3, a_c4 = tid & 7;          // +i*32 rows
    const int bn_n0 = tid >> 3, bn_c4 = tid & 7;          // non-trans
    const int bt_k0 = tid >> 4, bt_n4 = tid & 15;         // trans (+i*16 k)

    float4 pa[2], pb[2];
    const int nch = Kd >> 5;

    // prefetch chunk 0
#pragma unroll
    for (int i = 0; i < 2; i++)
        pa[i] = *(const float4*)(Ab + (long)(a_row0 + i * 32) * lda + (a_c4 << 2));
    if (!TRANSB) {
#pragma unroll
        for (int i = 0; i < 2; i++)
            pb[i] = *(const float4*)(Bb + (long)(bn_n0 + i * 32) * ldb + (bn_c4 << 2));
    } else {
#pragma unroll
        for (int i = 0; i < 2; i++)
            pb[i] = *(const float4*)(Bb + (long)(bt_k0 + i * 16) * ldb + (bt_n4 << 2));
    }

    for (int ch = 0; ch < nch; ch++) {
        // ---- convert + store staged regs into fragment-major SMEM ----
#pragma unroll
        for (int i = 0; i < 2; i++) {
            int row = a_row0 + i * 32;
            int kstep = a_c4 >> 1, chalf = a_c4 & 1;
            int base = (((kstep << 2) + (row >> 4)) << 5) + ((row & 7) << 2);
            int elem = ((row >> 3) & 1) + (chalf << 1);
            float vv[4] = {pa[i].x, pa[i].y, pa[i].z, pa[i].w};
#pragma unroll
            for (int j = 0; j < 4; j++) {
                float h = to_tf32(vv[j]);
                AsH[((base + j) << 2) + elem] = __float_as_uint(h);
                if (SPLIT)
                    AsL[((base + j) << 2) + elem] =
                        __float_as_uint(to_tf32(vv[j] - h));
            }
        }
        if (!TRANSB) {
#pragma unroll
            for (int i = 0; i < 2; i++) {
                int n = bn_n0 + i * 32;
                int kstep = bn_c4 >> 1, khalf = bn_c4 & 1;
                int base = (((kstep << 3) + (n >> 3)) << 5) + ((n & 7) << 2);
                float vv[4] = {pb[i].x, pb[i].y, pb[i].z, pb[i].w};
#pragma unroll
                for (int j = 0; j < 4; j++) {
                    float h = to_tf32(vv[j]);
                    BsH[((base + j) << 1) + khalf] = __float_as_uint(h);
                    if (SPLIT)
                        BsL[((base + j) << 1) + khalf] =
                            __float_as_uint(to_tf32(vv[j] - h));
                }
            }
        } else {
#pragma unroll
            for (int i = 0; i < 2; i++) {
                int k = bt_k0 + i * 16;
                int kstep = k >> 3, khalf = (k >> 2) & 1, kc = k & 3;
                float vv[4] = {pb[i].x, pb[i].y, pb[i].z, pb[i].w};
#pragma unroll
                for (int j = 0; j < 4; j++) {
                    int n = (bt_n4 << 2) + j;
                    int di = (((((kstep << 3) + (n >> 3)) << 5) +
                               ((n & 7) << 2) + kc) << 1) + khalf;
                    float h = to_tf32(vv[j]);
                    BsH[di] = __float_as_uint(h);
                    if (SPLIT) BsL[di] = __float_as_uint(to_tf32(vv[j] - h));
                }
            }
        }
        __syncthreads();

        // ---- issue next chunk's LDGs (overlap with HMMA below) ----
        if (ch + 1 < nch) {
            const int k0n = (ch + 1) << 5;
#pragma unroll
            for (int i = 0; i < 2; i++)
                pa[i] = *(const float4*)(Ab + (long)(a_row0 + i * 32) * lda +
                                         k0n + (a_c4 << 2));
            if (!TRANSB) {
#pragma unroll
                for (int i = 0; i < 2; i++)
                    pb[i] = *(const float4*)(Bb + (long)(bn_n0 + i * 32) * ldb +
                                             k0n + (bn_c4 << 2));
            } else {
#pragma unroll
                for (int i = 0; i < 2; i++)
                    pb[i] = *(const float4*)(Bb + (long)(k0n + bt_k0 + i * 16) * ldb +
                                             (bt_n4 << 2));
            }
        }

        // ---- compute: 4 k-steps of m16n8k8 ----
#pragma unroll
        for (int ks = 0; ks < 4; ks++) {
            uint32_t af[2][4], bf[2][2];
#pragma unroll
            for (int mi = 0; mi < 2; mi++) {
                uint4 t = *(const uint4*)
                    &AsH[((((ks << 2) + (wm << 1) + mi) << 5) + lane) << 2];
                af[mi][0] = t.x; af[mi][1] = t.y; af[mi][2] = t.z; af[mi][3] = t.w;
            }
#pragma unroll
            for (int nj = 0; nj < 2; nj++) {
                uint2 t = *(const uint2*)
                    &BsH[((((ks << 3) + (wn << 1) + nj) << 5) + lane) << 1];
                bf[nj][0] = t.x; bf[nj][1] = t.y;
            }
#pragma unroll
            for (int mi = 0; mi < 2; mi++)
#pragma unroll
                for (int nj = 0; nj < 2; nj++) MMA8(acc[mi][nj], af[mi], bf[nj]);
            if (SPLIT) {
                uint32_t al[2][4], bl[2][2];
#pragma unroll
                for (int mi = 0; mi < 2; mi++) {
                    uint4 t = *(const uint4*)
                        &AsL[((((ks << 2) + (wm << 1) + mi) << 5) + lane) << 2];
                    al[mi][0] = t.x; al[mi][1] = t.y; al[mi][2] = t.z; al[mi][3] = t.w;
                }
#pragma unroll
                for (int nj = 0; nj < 2; nj++) {
                    uint2 t = *(const uint2*)
                        &BsL[((((ks << 3) + (wn << 1) + nj) << 5) + lane) << 1];
                    bl[nj][0] = t.x; bl[nj][1] = t.y;
                }
#pragma unroll
                for (int mi = 0; mi < 2; mi++)
#pragma unroll
                    for (int nj = 0; nj < 2; nj++) {
                        MMA8(acc[mi][nj], af[mi], bl[nj]);
                        MMA8(acc[mi][nj], al[mi], bf[nj]);
                    }
            }
        }
        __syncthreads();
    }

    // ---- epilogue: direct fragment stores ----
    const float* bias_b = BIAS ? (bias + (long)bz * sBiasz) : (const float*)0;
#pragma unroll
    for (int mi = 0; mi < 2; mi++)
#pragma unroll
        for (int nj = 0; nj < 2; nj++) {
            int r = m0 + wm * 32 + mi * 16 + (lane >> 2);
            int c = n0 + wn * 16 + nj * 8 + ((lane & 3) << 1);
            float2 v0 = make_float2(acc[mi][nj][0], acc[mi][nj][1]);
            float2 v1 = make_float2(acc[mi][nj][2], acc[mi][nj][3]);
            if (BIAS) {
                float b0 = bias_b[c] * bscale, b1 = bias_b[c + 1] * bscale;
                v0.x += b0; v0.y += b1; v1.x += b0; v1.y += b1;
            }
            *(float2*)&Cb[(long)r * ldc + c] = v0;
            *(float2*)&Cb[(long)(r + 8) * ldc + c] = v1;
        }
}

// ---------------- RoPE ----------------------------------------------------
__global__ __launch_bounds__(DC_) void rope_kernel(const float* __restrict__ kv_c) {
    const int l = blockIdx.x;
    const int b = blockIdx.y;
    const int d = threadIdx.x;
    const long base = ((long)b * L_ + l) * DC_;
    float x = kv_c[base + d];
    float xr = (d < DC_ / 2) ? -kv_c[base + d + DC_ / 2] : kv_c[base + d - DC_ / 2];
    float ex = (float)(d & ~1) * (1.0f / (float)DC_);
    float inv = exp2f(-13.287712379549449f * ex);  // 10000^{-ex}
    float ang = (float)l * inv;
    float s, c;
    sincosf(ang, &s, &c);
    g_kv[base + d] = x * c + xr * s;
}

// ---------------- kvsum[b,d] = sum_l kv[b,l,d] ----------------------------
__global__ __launch_bounds__(128) void kvsum_kernel() {
    const int b = blockIdx.x;
    const int d = blockIdx.y * 128 + threadIdx.x;
    const float* p = g_kv + (long)b * L_ * DC_ + d;
    float s = 0.f;
#pragma unroll 8
    for (int l = 0; l < L_; l++) s += p[(long)l * DC_];
    g_kvsum[b * DC_ + d] = s;
}

// ---------------- scores[b,h,d] = kvsum[b,d] * sum_r qr[b,h,r]*Wkr[h,d,r] -
__global__ __launch_bounds__(256) void scores_kernel(const float* __restrict__ Wkr) {
    const int h = blockIdx.x;
    __shared__ __align__(16) float qs[B_][R_ + 4];
    __shared__ __align__(16) float ws[64][R_ + 4];
    const int tid = threadIdx.x;
    const int tcol = tid % 16;
    const int trow = tid / 16;

#pragma unroll
    for (int i = 0; i < 16; i++) {
        int idx = tid + i * 256;
        int b = idx >> 6, r = idx & 63;
        qs[b][r] = g_qr[((long)b * H_ + h) * R_ + r];
    }

    for (int d0 = 0; d0 < DC_; d0 += 64) {
        __syncthreads();
#pragma unroll
        for (int i = 0; i < 16; i++) {
            int idx = tid + i * 256;
            int dd = idx >> 6, r = idx & 63;
            ws[dd][r] = Wkr[((long)h * DC_ + d0 + dd) * R_ + r];
        }
        __syncthreads();
        float acc[4][4];
#pragma unroll
        for (int i = 0; i < 4; i++)
#pragma unroll
            for (int j = 0; j < 4; j++) acc[i][j] = 0.f;
#pragma unroll 8
        for (int r = 0; r < R_; r++) {
            float a[4], bv[4];
#pragma unroll
            for (int i = 0; i < 4; i++) a[i] = qs[trow * 4 + i][r];
#pragma unroll
            for (int j = 0; j < 4; j++) bv[j] = ws[tcol * 4 + j][r];
#pragma unroll
            for (int i = 0; i < 4; i++)
#pragma unroll
                for (int j = 0; j < 4; j++) acc[i][j] += a[i] * bv[j];
        }
#pragma unroll
        for (int i = 0; i < 4; i++) {
            int b = trow * 4 + i;
#pragma unroll
            for (int j = 0; j < 4; j++) {
                int d = d0 + tcol * 4 + j;
                g_scores[((long)b * H_ + h) * DC_ + d] = acc[i][j] * g_kvsum[b * DC_ + d];
            }
        }
    }
}

// ---------------- softmax, then subtract uniform mode 1/512 ---------------
__global__ __launch_bounds__(128) void softmax_kernel() {
    const int bh = blockIdx.x;
    float* p = g_scores + (long)bh * DC_;
    const int tid = threadIdx.x;
    __shared__ float red[128];
    float v[4];
    float mx = -1e30f;
#pragma unroll
    for (int i = 0; i < 4; i++) {
        v[i] = p[tid + i * 128];
        mx = fmaxf(mx, v[i]);
    }
    red[tid] = mx;
    __syncthreads();
    for (int s = 64; s > 0; s >>= 1) {
        if (tid < s) red[tid] = fmaxf(red[tid], red[tid + s]);
        __syncthreads();
    }
    mx = red[0];
    __syncthreads();
    float sum = 0.f;
#pragma unroll
    for (int i = 0; i < 4; i++) {
        v[i] = expf(v[i] - mx);
        sum += v[i];
    }
    red[tid] = sum;
    __syncthreads();
    for (int s = 64; s > 0; s >>= 1) {
        if (tid < s) red[tid] += red[tid + s];
        __syncthreads();
    }
    float invs = 1.0f / red[0];
#pragma unroll
    for (int i = 0; i < 4; i++)
        p[tid + i * 128] = v[i] * invs - (1.0f / 512.0f);
}

// ---------------- split-K reduce into d_out -------------------------------
__global__ __launch_bounds__(256) void reduce_kernel(float* __restrict__ out) {
    const int i = blockIdx.x * 256 + threadIdx.x;
    float s = 0.f;
#pragma unroll
    for (int z = 0; z < SPLITS_; z++) s += g_part[(long)z * B_ * DQ_ + i];
    out[i] = s;
}

// ---------------- launch --------------------------------------------------
extern "C" void kernel_launch(void* const* d_in, const int* in_sizes, int n_in,
                              void* d_out, int out_size) {
    const float* hidden_q   = (const float*)d_in[0];
    const float* kv_c       = (const float*)d_in[1];
    const float* q_proj_w   = (const float*)d_in[2];
    const float* w_kc_q     = (const float*)d_in[3];
    const float* w_kc_kv    = (const float*)d_in[4];
    const float* W_qr       = (const float*)d_in[5];
    const float* W_kr       = (const float*)d_in[6];
    const float* out_proj_w = (const float*)d_in[7];
    float* out = (float*)d_out;

    float *qhk, *Ah, *qr, *kvsum, *scores, *ctx, *ctxlat, *part, *kv;
    cudaGetSymbolAddress((void**)&qhk,    g_qhk);
    cudaGetSymbolAddress((void**)&Ah,     g_Ah);
    cudaGetSymbolAddress((void**)&qr,     g_qr);
    cudaGetSymbolAddress((void**)&kv,     g_kv);
    cudaGetSymbolAddress((void**)&kvsum,  g_kvsum);
    cudaGetSymbolAddress((void**)&scores, g_scores);
    cudaGetSymbolAddress((void**)&ctx,    g_ctx);
    cudaGetSymbolAddress((void**)&ctxlat, g_ctxlat);
    cudaGetSymbolAddress((void**)&part,   g_part);

    rope_kernel<<<dim3(L_, B_), DC_>>>(kv_c);
    kvsum_kernel<<<dim3(B_, 4), 128>>>();

    // q_hk = hidden_q @ q_proj_w^T   [64 x 16384], K=2048
    mgemm<false, false, false><<<dim3(256, 1, 1), 256>>>(
        hidden_q, q_proj_w, qhk, (const float*)0, 0.f, 0,
        DQ_, 0, 0, 0, DQ_, DQ_, H_ * KH_);

    // A_h = w_kc_q[h] @ W_qr[h]   (B source [q,r] -> trans)  [128 x 64] x128
    mgemm<true, false, false><<<dim3(1, 2, H_), 256>>>(
        w_kc_q, W_qr, Ah, (const float*)0, 0.f, 0,
        DCQ_, (long)KH_ * DCQ_, (long)DCQ_ * R_, (long)KH_ * R_,
        DCQ_, R_, R_);

    // q_r = q_hk[:,h,:] @ A_h   (B source [k,r] -> trans)  [64 x 64] x128
    mgemm<true, false, false><<<dim3(1, 1, H_), 256>>>(
        qhk, Ah, qr, (const float*)0, 0.f, 0,
        KH_, (long)KH_, (long)KH_ * R_, (long)R_, H_ * KH_, R_, H_ * R_);

    scores_kernel<<<H_, 256>>>(W_kr);
    softmax_kernel<<<B_ * H_, 128>>>();

    // ctx = (attn - 1/512) @ kv + kvsum/512  (B source [j,d] -> trans, bias)
    mgemm<true, false, true><<<dim3(DC_ / 64, 2, B_), 256>>>(
        scores, kv, ctx, kvsum, 1.0f / 512.0f, (long)DC_,
        DC_, (long)H_ * DC_, (long)L_ * DC_, (long)H_ * DC_,
        DC_, DC_, DC_);

    // ctxlat = ctx[:,h,:] @ w_kc_kv[h]^T   (3xTF32 split)  [64 x 128] x128
    mgemm<false, true, false><<<dim3(KH_ / 64, 1, H_), 256>>>(
        ctx, w_kc_kv, ctxlat, (const float*)0, 0.f, 0,
        DC_, (long)DC_, (long)KH_ * DC_, (long)KH_, H_ * DC_, DC_, H_ * KH_);

    // out = ctxlat @ out_proj_w^T  (3xTF32 split, split-K x16)
    mgemm<false, true, false><<<dim3(DQ_ / 64, 1, SPLITS_), 256>>>(
        ctxlat, out_proj_w, part, (const float*)0, 0.f, 0,
        H_ * KH_ / SPLITS_,
        (long)(H_ * KH_ / SPLITS_), (long)(H_ * KH_ / SPLITS_), (long)B_ * DQ_,
        H_ * KH_, H_ * KH_, DQ_);
    reduce_kernel<<<B_ * DQ_ / 256, 256>>>(out);
}

// round 6
// speedup vs baseline: 1.2349x; 1.0591x over previous
#include <cuda_runtime.h>
#include <math.h>
#include <stdint.h>

#define B_   64
#define L_   512
#define DQ_  2048
#define H_   128
#define KH_  128
#define DC_  512
#define DCQ_ 1536
#define R_   64
#define SPLITS_ 16

// ---------------- scratch (device globals; no allocation allowed) ----------
__device__ float g_qhk[B_ * H_ * KH_];
__device__ float g_Ah[H_ * KH_ * R_];
__device__ float g_qr[B_ * H_ * R_];
__device__ float g_kv[B_ * L_ * DC_];
__device__ float g_kvsum[B_ * DC_];
__device__ float g_scores[B_ * H_ * DC_];
__device__ float g_ctx[B_ * H_ * DC_];
__device__ float g_ctxlat[B_ * H_ * KH_];
__device__ float g_part[SPLITS_ * B_ * DQ_];

// ---------------- helpers --------------------------------------------------
__device__ __forceinline__ float to_tf32(float x) {
    float y; asm("cvt.rna.tf32.f32 %0, %1;" : "=f"(y) : "f"(x)); return y;
}

#define MMA8(d, a, b)                                                         \
    asm volatile(                                                             \
        "mma.sync.aligned.m16n8k8.row.col.f32.tf32.tf32.f32 "                 \
        "{%0,%1,%2,%3}, {%4,%5,%6,%7}, {%8,%9}, {%0,%1,%2,%3};"               \
        : "+f"((d)[0]), "+f"((d)[1]), "+f"((d)[2]), "+f"((d)[3])              \
        : "r"((a)[0]), "r"((a)[1]), "r"((a)[2]), "r"((a)[3]),                 \
          "r"((b)[0]), "r"((b)[1]))

// ---- staging: regs -> fragment-major SMEM (with tf32 RNA conversion) ------
template <bool SPLIT>
__device__ __forceinline__ void sts_a(uint32_t* AsH, uint32_t* AsL,
                                      const float4* pa, int a_row0, int a_c4) {
#pragma unroll
    for (int i = 0; i < 2; i++) {
        int row = a_row0 + i * 32;
        int kstep = a_c4 >> 1, chalf = a_c4 & 1;
        int base = (((kstep << 2) + (row >> 4)) << 5) + ((row & 7) << 2);
        int elem = ((row >> 3) & 1) + (chalf << 1);
        float vv[4] = {pa[i].x, pa[i].y, pa[i].z, pa[i].w};
#pragma unroll
        for (int j = 0; j < 4; j++) {
            float h = to_tf32(vv[j]);
            AsH[((base + j) << 2) + elem] = __float_as_uint(h);
            if (SPLIT)
                AsL[((base + j) << 2) + elem] = __float_as_uint(to_tf32(vv[j] - h));
        }
    }
}

template <bool SPLIT, bool TRANSB>
__device__ __forceinline__ void sts_b(uint32_t* BsH, uint32_t* BsL,
                                      const float4* pb, int c0, int c1) {
    if (!TRANSB) {
        // c0 = bn_n0, c1 = bn_c4
#pragma unroll
        for (int i = 0; i < 2; i++) {
            int n = c0 + i * 32;
            int kstep = c1 >> 1, khalf = c1 & 1;
            int base = (((kstep << 3) + (n >> 3)) << 5) + ((n & 7) << 2);
            float vv[4] = {pb[i].x, pb[i].y, pb[i].z, pb[i].w};
#pragma unroll
            for (int j = 0; j < 4; j++) {
                float h = to_tf32(vv[j]);
                BsH[((base + j) << 1) + khalf] = __float_as_uint(h);
                if (SPLIT)
                    BsL[((base + j) << 1) + khalf] = __float_as_uint(to_tf32(vv[j] - h));
            }
        }
    } else {
        // c0 = bt_k0, c1 = bt_n4
#pragma unroll
        for (int i = 0; i < 2; i++) {
            int k = c0 + i * 16;
            int kstep = k >> 3, khalf = (k >> 2) & 1, kc = k & 3;
            float vv[4] = {pb[i].x, pb[i].y, pb[i].z, pb[i].w};
#pragma unroll
            for (int j = 0; j < 4; j++) {
                int n = (c1 << 2) + j;
                int di = (((((kstep << 3) + (n >> 3)) << 5) +
                           ((n & 7) << 2) + kc) << 1) + khalf;
                float h = to_tf32(vv[j]);
                BsH[di] = __float_as_uint(h);
                if (SPLIT) BsL[di] = __float_as_uint(to_tf32(vv[j] - h));
            }
        }
    }
}

// ---- compute one 32-k chunk (4 k-steps of m16n8k8) ------------------------
template <bool SPLIT>
__device__ __forceinline__ void compute_chunk(
    const uint32_t* AsH, const uint32_t* BsH,
    const uint32_t* AsL, const uint32_t* BsL,
    float acc[2][2][4], int wm, int wn, int lane) {
#pragma unroll
    for (int ks = 0; ks < 4; ks++) {
        uint32_t af[2][4], bf[2][2];
#pragma unroll
        for (int mi = 0; mi < 2; mi++) {
            uint4 t = *(const uint4*)
                &AsH[((((ks << 2) + (wm << 1) + mi) << 5) + lane) << 2];
            af[mi][0] = t.x; af[mi][1] = t.y; af[mi][2] = t.z; af[mi][3] = t.w;
        }
#pragma unroll
        for (int nj = 0; nj < 2; nj++) {
            uint2 t = *(const uint2*)
                &BsH[((((ks << 3) + (wn << 1) + nj) << 5) + lane) << 1];
            bf[nj][0] = t.x; bf[nj][1] = t.y;
        }
#pragma unroll
        for (int mi = 0; mi < 2; mi++)
#pragma unroll
            for (int nj = 0; nj < 2; nj++) MMA8(acc[mi][nj], af[mi], bf[nj]);
        if (SPLIT) {
            uint32_t al[2][4], bl[2][2];
#pragma unroll
            for (int mi = 0; mi < 2; mi++) {
                uint4 t = *(const uint4*)
                    &AsL[((((ks << 2) + (wm << 1) + mi) << 5) + lane) << 2];
                al[mi][0] = t.x; al[mi][1] = t.y; al[mi][2] = t.z; al[mi][3] = t.w;
            }
#pragma unroll
            for (int nj = 0; nj < 2; nj++) {
                uint2 t = *(const uint2*)
                    &BsL[((((ks << 3) + (wn << 1) + nj) << 5) + lane) << 1];
                bl[nj][0] = t.x; bl[nj][1] = t.y;
            }
#pragma unroll
            for (int mi = 0; mi < 2; mi++)
#pragma unroll
                for (int nj = 0; nj < 2; nj++) {
                    MMA8(acc[mi][nj], af[mi], bl[nj]);
                    MMA8(acc[mi][nj], al[mi], bf[nj]);
                }
        }
    }
}

// ---------------- tf32 mma.sync GEMM  (BM=64, BN=64, BK=32, 256 thr) -------
// C[m,n] = sum_k A[m,k] * B[n,k].  TRANSB: B source is [K,N] row-major.
// SPLIT: 3xTF32 hi/lo error-compensated path (single-stage, reg prefetch).
// Non-split: 2-stage SMEM double buffer, prefetch distance 2.
// BIAS: C += bias[n]*bscale.
template <bool TRANSB, bool SPLIT, bool BIAS>
__global__ __launch_bounds__(256)
void mgemm(const float* __restrict__ A, const float* __restrict__ Bm,
           float* __restrict__ C, const float* __restrict__ bias,
           float bscale, long sBiasz, int Kd,
           long sAz, long sBz, long sCz, int lda, int ldb, int ldc) {
    __shared__ uint32_t AsH[(SPLIT ? 1 : 2) * 2048], BsH[(SPLIT ? 1 : 2) * 2048];
    __shared__ uint32_t AsL[SPLIT ? 2048 : 4], BsL[SPLIT ? 2048 : 4];

    const int tid = threadIdx.x, lane = tid & 31, wid = tid >> 5;
    const int wm = wid >> 2, wn = wid & 3;
    const int n0 = blockIdx.x * 64, m0 = blockIdx.y * 64, bz = blockIdx.z;

    const float* Ab = A + (long)bz * sAz + (long)m0 * lda;
    const float* Bb = TRANSB ? (Bm + (long)bz * sBz + n0)
                             : (Bm + (long)bz * sBz + (long)n0 * ldb);
    float* Cb = C + (long)bz * sCz;

    float acc[2][2][4];
#pragma unroll
    for (int mi = 0; mi < 2; mi++)
#pragma unroll
        for (int nj = 0; nj < 2; nj++)
#pragma unroll
            for (int e = 0; e < 4; e++) acc[mi][nj][e] = 0.f;

    const int a_row0 = tid >> 3, a_c4 = tid & 7;
    const int bn_n0 = tid >> 3, bn_c4 = tid & 7;
    const int bt_k0 = tid >> 4, bt_n4 = tid & 15;

    float4 pa[2], pb[2];
    const int nch = Kd >> 5;

#define LDG_CH(k0v)                                                           \
    do {                                                                      \
        _Pragma("unroll")                                                     \
        for (int i = 0; i < 2; i++)                                           \
            pa[i] = *(const float4*)(Ab + (long)(a_row0 + i * 32) * lda +     \
                                     (k0v) + (a_c4 << 2));                    \
        if (!TRANSB) {                                                        \
            _Pragma("unroll")                                                 \
            for (int i = 0; i < 2; i++)                                       \
                pb[i] = *(const float4*)(Bb + (long)(bn_n0 + i * 32) * ldb +  \
                                         (k0v) + (bn_c4 << 2));               \
        } else {                                                              \
            _Pragma("unroll")                                                 \
            for (int i = 0; i < 2; i++)                                       \
                pb[i] = *(const float4*)(Bb +                                 \
                         (long)((k0v) + bt_k0 + i * 16) * ldb + (bt_n4 << 2));\
        }                                                                     \
    } while (0)

    if (!SPLIT) {
        // ---- 2-stage pipeline, prefetch distance 2 ----
        LDG_CH(0);
        sts_a<false>(AsH, AsL, pa, a_row0, a_c4);
        sts_b<false, TRANSB>(BsH, BsL, pb, TRANSB ? bt_k0 : bn_n0,
                             TRANSB ? bt_n4 : bn_c4);
        LDG_CH(32);
        __syncthreads();
        for (int ch = 0; ch < nch; ch++) {
            const int cur = ch & 1;
            if (ch + 1 < nch) {
                uint32_t* aD = AsH + (1 - cur) * 2048;
                uint32_t* bD = BsH + (1 - cur) * 2048;
                sts_a<false>(aD, AsL, pa, a_row0, a_c4);
                sts_b<false, TRANSB>(bD, BsL, pb, TRANSB ? bt_k0 : bn_n0,
                                     TRANSB ? bt_n4 : bn_c4);
                if (ch + 2 < nch) LDG_CH((ch + 2) << 5);
            }
            compute_chunk<false>(AsH + cur * 2048, BsH + cur * 2048,
                                 AsL, BsL, acc, wm, wn, lane);
            __syncthreads();
        }
    } else {
        // ---- single-stage, register prefetch distance 1 (3xTF32 path) ----
        LDG_CH(0);
        for (int ch = 0; ch < nch; ch++) {
            sts_a<true>(AsH, AsL, pa, a_row0, a_c4);
            sts_b<true, TRANSB>(BsH, BsL, pb, TRANSB ? bt_k0 : bn_n0,
                                TRANSB ? bt_n4 : bn_c4);
            __syncthreads();
            if (ch + 1 < nch) LDG_CH((ch + 1) << 5);
            compute_chunk<true>(AsH, BsH, AsL, BsL, acc, wm, wn, lane);
            __syncthreads();
        }
    }
#undef LDG_CH

    // ---- epilogue: direct fragment stores ----
    const float* bias_b = BIAS ? (bias + (long)bz * sBiasz) : (const float*)0;
#pragma unroll
    for (int mi = 0; mi < 2; mi++)
#pragma unroll
        for (int nj = 0; nj < 2; nj++) {
            int r = m0 + wm * 32 + mi * 16 + (lane >> 2);
            int c = n0 + wn * 16 + nj * 8 + ((lane & 3) << 1);
            float2 v0 = make_float2(acc[mi][nj][0], acc[mi][nj][1]);
            float2 v1 = make_float2(acc[mi][nj][2], acc[mi][nj][3]);
            if (BIAS) {
                float b0 = bias_b[c] * bscale, b1 = bias_b[c + 1] * bscale;
                v0.x += b0; v0.y += b1; v1.x += b0; v1.y += b1;
            }
            *(float2*)&Cb[(long)r * ldc + c] = v0;
            *(float2*)&Cb[(long)(r + 8) * ldc + c] = v1;
        }
}

// ---------------- RoPE (paired: thread d handles d and d+256) -------------
__global__ __launch_bounds__(256) void rope_kernel(const float* __restrict__ kv_c) {
    const int l = blockIdx.x;
    const int b = blockIdx.y;
    const int d = threadIdx.x;  // 0..255
    const long base = ((long)b * L_ + l) * DC_;
    float x0 = kv_c[base + d];
    float x1 = kv_c[base + d + 256];
    // angle for index d
    float ex0 = (float)(d & ~1) * (1.0f / (float)DC_);
    float inv0 = exp2f(-13.287712379549449f * ex0);
    float s0, c0;
    sincosf((float)l * inv0, &s0, &c0);
    // angle for index d+256
    float ex1 = (float)((d + 256) & ~1) * (1.0f / (float)DC_);
    float inv1 = exp2f(-13.287712379549449f * ex1);
    float s1, c1;
    sincosf((float)l * inv1, &s1, &c1);
    g_kv[base + d] = x0 * c0 - x1 * s0;        // rotate_half low: -x[d+256]
    g_kv[base + d + 256] = x1 * c1 + x0 * s1;  // rotate_half high: +x[d]
}

// ---------------- kvsum[b,d] = sum_l kv[b,l,d] ----------------------------
__global__ __launch_bounds__(128) void kvsum_kernel() {
    const int b = blockIdx.x;
    const int d = blockIdx.y * 128 + threadIdx.x;
    const float* p = g_kv + (long)b * L_ * DC_ + d;
    float s = 0.f;
#pragma unroll 8
    for (int l = 0; l < L_; l++) s += p[(long)l * DC_];
    g_kvsum[b * DC_ + d] = s;
}

// ---------------- scores[b,h,d] = kvsum[b,d] * sum_r qr[b,h,r]*Wkr[h,d,r] -
__global__ __launch_bounds__(256) void scores_kernel(const float* __restrict__ Wkr) {
    const int h = blockIdx.x;
    __shared__ __align__(16) float qs[B_][R_ + 4];
    __shared__ __align__(16) float ws[64][R_ + 4];
    const int tid = threadIdx.x;
    const int tcol = tid % 16;
    const int trow = tid / 16;

#pragma unroll
    for (int i = 0; i < 16; i++) {
        int idx = tid + i * 256;
        int b = idx >> 6, r = idx & 63;
        qs[b][r] = g_qr[((long)b * H_ + h) * R_ + r];
    }

    for (int d0 = 0; d0 < DC_; d0 += 64) {
        __syncthreads();
#pragma unroll
        for (int i = 0; i < 16; i++) {
            int idx = tid + i * 256;
            int dd = idx >> 6, r = idx & 63;
            ws[dd][r] = Wkr[((long)h * DC_ + d0 + dd) * R_ + r];
        }
        __syncthreads();
        float acc[4][4];
#pragma unroll
        for (int i = 0; i < 4; i++)
#pragma unroll
            for (int j = 0; j < 4; j++) acc[i][j] = 0.f;
#pragma unroll 8
        for (int r = 0; r < R_; r++) {
            float a[4], bv[4];
#pragma unroll
            for (int i = 0; i < 4; i++) a[i] = qs[trow * 4 + i][r];
#pragma unroll
            for (int j = 0; j < 4; j++) bv[j] = ws[tcol * 4 + j][r];
#pragma unroll
            for (int i = 0; i < 4; i++)
#pragma unroll
                for (int j = 0; j < 4; j++) acc[i][j] += a[i] * bv[j];
        }
#pragma unroll
        for (int i = 0; i < 4; i++) {
            int b = trow * 4 + i;
#pragma unroll
            for (int j = 0; j < 4; j++) {
                int d = d0 + tcol * 4 + j;
                g_scores[((long)b * H_ + h) * DC_ + d] = acc[i][j] * g_kvsum[b * DC_ + d];
            }
        }
    }
}

// ---------------- softmax, then subtract uniform mode 1/512 ---------------
__global__ __launch_bounds__(128) void softmax_kernel() {
    const int bh = blockIdx.x;
    float* p = g_scores + (long)bh * DC_;
    const int tid = threadIdx.x;
    __shared__ float red[128];
    float v[4];
    float mx = -1e30f;
#pragma unroll
    for (int i = 0; i < 4; i++) {
        v[i] = p[tid + i * 128];
        mx = fmaxf(mx, v[i]);
    }
    red[tid] = mx;
    __syncthreads();
    for (int s = 64; s > 0; s >>= 1) {
        if (tid < s) red[tid] = fmaxf(red[tid], red[tid + s]);
        __syncthreads();
    }
    mx = red[0];
    __syncthreads();
    float sum = 0.f;
#pragma unroll
    for (int i = 0; i < 4; i++) {
        v[i] = expf(v[i] - mx);
        sum += v[i];
    }
    red[tid] = sum;
    __syncthreads();
    for (int s = 64; s > 0; s >>= 1) {
        if (tid < s) red[tid] += red[tid + s];
        __syncthreads();
    }
    float invs = 1.0f / red[0];
#pragma unroll
    for (int i = 0; i < 4; i++)
        p[tid + i * 128] = v[i] * invs - (1.0f / 512.0f);
}

// ---------------- split-K reduce into d_out -------------------------------
__global__ __launch_bounds__(256) void reduce_kernel(float* __restrict__ out) {
    const int i = blockIdx.x * 256 + threadIdx.x;
    float s = 0.f;
#pragma unroll
    for (int z = 0; z < SPLITS_; z++) s += g_part[(long)z * B_ * DQ_ + i];
    out[i] = s;
}

// ---------------- launch --------------------------------------------------
extern "C" void kernel_launch(void* const* d_in, const int* in_sizes, int n_in,
                              void* d_out, int out_size) {
    const float* hidden_q   = (const float*)d_in[0];
    const float* kv_c       = (const float*)d_in[1];
    const float* q_proj_w   = (const float*)d_in[2];
    const float* w_kc_q     = (const float*)d_in[3];
    const float* w_kc_kv    = (const float*)d_in[4];
    const float* W_qr       = (const float*)d_in[5];
    const float* W_kr       = (const float*)d_in[6];
    const float* out_proj_w = (const float*)d_in[7];
    float* out = (float*)d_out;

    float *qhk, *Ah, *qr, *kvsum, *scores, *ctx, *ctxlat, *part, *kv;
    cudaGetSymbolAddress((void**)&qhk,    g_qhk);
    cudaGetSymbolAddress((void**)&Ah,     g_Ah);
    cudaGetSymbolAddress((void**)&qr,     g_qr);
    cudaGetSymbolAddress((void**)&kv,     g_kv);
    cudaGetSymbolAddress((void**)&kvsum,  g_kvsum);
    cudaGetSymbolAddress((void**)&scores, g_scores);
    cudaGetSymbolAddress((void**)&ctx,    g_ctx);
    cudaGetSymbolAddress((void**)&ctxlat, g_ctxlat);
    cudaGetSymbolAddress((void**)&part,   g_part);

    rope_kernel<<<dim3(L_, B_), 256>>>(kv_c);
    kvsum_kernel<<<dim3(B_, 4), 128>>>();

    // q_hk = hidden_q @ q_proj_w^T   [64 x 16384], K=2048
    mgemm<false, false, false><<<dim3(256, 1, 1), 256>>>(
        hidden_q, q_proj_w, qhk, (const float*)0, 0.f, 0,
        DQ_, 0, 0, 0, DQ_, DQ_, H_ * KH_);

    // A_h = w_kc_q[h] @ W_qr[h]   (B source [q,r] -> trans)  [128 x 64] x128
    mgemm<true, false, false><<<dim3(1, 2, H_), 256>>>(
        w_kc_q, W_qr, Ah, (const float*)0, 0.f, 0,
        DCQ_, (long)KH_ * DCQ_, (long)DCQ_ * R_, (long)KH_ * R_,
        DCQ_, R_, R_);

    // q_r = q_hk[:,h,:] @ A_h   (B source [k,r] -> trans)  [64 x 64] x128
    mgemm<true, false, false><<<dim3(1, 1, H_), 256>>>(
        qhk, Ah, qr, (const float*)0, 0.f, 0,
        KH_, (long)KH_, (long)KH_ * R_, (long)R_, H_ * KH_, R_, H_ * R_);

    scores_kernel<<<H_, 256>>>(W_kr);
    softmax_kernel<<<B_ * H_, 128>>>();

    // ctx = (attn - 1/512) @ kv + kvsum/512  (B source [j,d] -> trans, bias)
    mgemm<true, false, true><<<dim3(DC_ / 64, 2, B_), 256>>>(
        scores, kv, ctx, kvsum, 1.0f / 512.0f, (long)DC_,
        DC_, (long)H_ * DC_, (long)L_ * DC_, (long)H_ * DC_,
        DC_, DC_, DC_);

    // ctxlat = ctx[:,h,:] @ w_kc_kv[h]^T   (3xTF32 split)  [64 x 128] x128
    mgemm<false, true, false><<<dim3(KH_ / 64, 1, H_), 256>>>(
        ctx, w_kc_kv, ctxlat, (const float*)0, 0.f, 0,
        DC_, (long)DC_, (long)KH_ * DC_, (long)KH_, H_ * DC_, DC_, H_ * KH_);

    // out = ctxlat @ out_proj_w^T  (3xTF32 split, split-K x16)
    mgemm<false, true, false><<<dim3(DQ_ / 64, 1, SPLITS_), 256>>>(
        ctxlat, out_proj_w, part, (const float*)0, 0.f, 0,
        H_ * KH_ / SPLITS_,
        (long)(H_ * KH_ / SPLITS_), (long)(H_ * KH_ / SPLITS_), (long)B_ * DQ_,
        H_ * KH_, H_ * KH_, DQ_);
    reduce_kernel<<<B_ * DQ_ / 256, 256>>>(out);
}

// round 7
// speedup vs baseline: 2.2096x; 1.7893x over previous
#include <cuda_runtime.h>
#include <cuda_bf16.h>
#include <math.h>
#include <stdint.h>

#define B_   64
#define L_   512
#define DQ_  2048
#define H_   128
#define KH_  128
#define DC_  512
#define DCQ_ 1536
#define R_   64
#define SPLITS_ 16

// ---------------- scratch (device globals; no allocation allowed) ----------
__device__ float g_qhk[B_ * H_ * KH_];
__device__ float g_Ah[H_ * KH_ * R_];
__device__ float g_qr[B_ * H_ * R_];
__device__ float g_kv[B_ * L_ * DC_];
__device__ float g_kvsum[B_ * DC_];
__device__ float g_scores[B_ * H_ * DC_];
__device__ float g_ctx[B_ * H_ * DC_];
__device__ float g_ctxlat[B_ * H_ * KH_];
__device__ float g_part[SPLITS_ * B_ * DQ_];

// ---------------- bf16 helpers ---------------------------------------------
// split float4 -> 4 bf16 hi (uint2) + 4 bf16 lo (uint2), k-contiguous pairs
__device__ __forceinline__ void bsplit4(float4 v, uint2& hi, uint2& lo) {
    uint32_t h01, h23, l01, l23;
    asm("cvt.rn.bf16x2.f32 %0, %1, %2;" : "=r"(h01) : "f"(v.y), "f"(v.x));
    asm("cvt.rn.bf16x2.f32 %0, %1, %2;" : "=r"(h23) : "f"(v.w), "f"(v.z));
    float r0 = v.x - __uint_as_float(h01 << 16);
    float r1 = v.y - __uint_as_float(h01 & 0xFFFF0000u);
    float r2 = v.z - __uint_as_float(h23 << 16);
    float r3 = v.w - __uint_as_float(h23 & 0xFFFF0000u);
    asm("cvt.rn.bf16x2.f32 %0, %1, %2;" : "=r"(l01) : "f"(r1), "f"(r0));
    asm("cvt.rn.bf16x2.f32 %0, %1, %2;" : "=r"(l23) : "f"(r3), "f"(r2));
    hi.x = h01; hi.y = h23; lo.x = l01; lo.y = l23;
}

#define LDMX4(r, a)                                                           \
    asm volatile("ldmatrix.sync.aligned.m8n8.x4.shared.b16 {%0,%1,%2,%3}, [%4];" \
                 : "=r"((r)[0]), "=r"((r)[1]), "=r"((r)[2]), "=r"((r)[3])     \
                 : "r"(a))
#define LDMX2(r, a)                                                           \
    asm volatile("ldmatrix.sync.aligned.m8n8.x2.shared.b16 {%0,%1}, [%2];"    \
                 : "=r"((r)[0]), "=r"((r)[1]) : "r"(a))
#define LDMX2T(r, a)                                                          \
    asm volatile("ldmatrix.sync.aligned.m8n8.x2.trans.shared.b16 {%0,%1}, [%2];" \
                 : "=r"((r)[0]), "=r"((r)[1]) : "r"(a))

#define MMAB(d, a, b)                                                         \
    asm volatile(                                                             \
        "mma.sync.aligned.m16n8k16.row.col.f32.bf16.bf16.f32 "                \
        "{%0,%1,%2,%3}, {%4,%5,%6,%7}, {%8,%9}, {%0,%1,%2,%3};"               \
        : "+f"((d)[0]), "+f"((d)[1]), "+f"((d)[2]), "+f"((d)[3])              \
        : "r"((a)[0]), "r"((a)[1]), "r"((a)[2]), "r"((a)[3]),                 \
          "r"((b)[0]), "r"((b)[1]))

// ---------------- 3xBF16 mma.sync GEMM  (BM=64, BN=64, BK=32, 256 thr) -----
// C[m,n] = sum_k A[m,k] * B[n,k].  TRANSB: B source is [K,N] row-major.
// All operands hi/lo-split bf16; per k16 step: 3 MMAs (hh + hl + lh).
// 2-stage SMEM double buffer, prefetch distance 2. BIAS: C += bias[n]*bscale.
// SMEM per stage: A hi [64][80B] | A lo | B hi | B lo
//   A/Bn layout: [row][k] bf16, pitch 80B (conflict-free ldmatrix: 5r mod 8)
//   Bt  layout:  [k][n] bf16, pitch 144B (9k mod 8), frags via ldmatrix.trans
#define PA_    80
#define PB_T   144
#define A_HI_  0
#define A_LO_  5120
#define B_HI_  10240
#define B_LO_  15360
#define STAGE_ 20480

template <bool TRANSB, bool BIAS>
__global__ __launch_bounds__(256)
void mgemm(const float* __restrict__ A, const float* __restrict__ Bm,
           float* __restrict__ C, const float* __restrict__ bias,
           float bscale, long sBiasz, int Kd,
           long sAz, long sBz, long sCz, int lda, int ldb, int ldc) {
    __shared__ __align__(16) char sm[2 * STAGE_];

    const int tid = threadIdx.x, lane = tid & 31, wid = tid >> 5;
    const int wm = wid >> 2, wn = wid & 3;
    const int n0 = blockIdx.x * 64, m0 = blockIdx.y * 64, bz = blockIdx.z;

    const float* Ab = A + (long)bz * sAz + (long)m0 * lda;
    const float* Bb = TRANSB ? (Bm + (long)bz * sBz + n0)
                             : (Bm + (long)bz * sBz + (long)n0 * ldb);
    float* Cb = C + (long)bz * sCz;

    float acc[2][2][4];
#pragma unroll
    for (int mi = 0; mi < 2; mi++)
#pragma unroll
        for (int nj = 0; nj < 2; nj++)
#pragma unroll
            for (int e = 0; e < 4; e++) acc[mi][nj][e] = 0.f;

    // staging coords
    const int a_row0 = tid >> 3, a_c4 = tid & 7;     // A & B non-trans
    const int bt_k0 = tid >> 4, bt_n4 = tid & 15;    // B trans

    // ldmatrix lane offsets (byte offsets within a stage)
    const int lane7 = lane & 7, laneb = (lane >> 3) & 1, lanet = lane >> 4;
    uint32_t aoff[2][2], boff[2][2];
#pragma unroll
    for (int mi = 0; mi < 2; mi++)
#pragma unroll
        for (int s = 0; s < 2; s++)
            aoff[mi][s] = (uint32_t)((wm * 32 + mi * 16 + lane7 + laneb * 8) * PA_ +
                                     (s * 16 + lanet * 8) * 2);
#pragma unroll
    for (int nj = 0; nj < 2; nj++)
#pragma unroll
        for (int s = 0; s < 2; s++) {
            if (TRANSB)
                boff[nj][s] = (uint32_t)((s * 16 + laneb * 8 + lane7) * PB_T +
                                         (wn * 16 + nj * 8) * 2);
            else
                boff[nj][s] = (uint32_t)((wn * 16 + nj * 8 + lane7) * PA_ +
                                         (s * 16 + laneb * 8) * 2);
        }
    const uint32_t smb = (uint32_t)__cvta_generic_to_shared(sm);

    float4 pa[2], pb[2];
    const int nch = Kd >> 5;

#define LDG_CH(k0v)                                                           \
    do {                                                                      \
        _Pragma("unroll")                                                     \
        for (int i = 0; i < 2; i++)                                           \
            pa[i] = *(const float4*)(Ab + (long)(a_row0 + i * 32) * lda +     \
                                     (k0v) + (a_c4 << 2));                    \
        if (!TRANSB) {                                                        \
            _Pragma("unroll")                                                 \
            for (int i = 0; i < 2; i++)                                       \
                pb[i] = *(const float4*)(Bb + (long)(a_row0 + i * 32) * ldb + \
                                         (k0v) + (a_c4 << 2));                \
        } else {                                                              \
            _Pragma("unroll")                                                 \
            for (int i = 0; i < 2; i++)                                       \
                pb[i] = *(const float4*)(Bb +                                 \
                         (long)((k0v) + bt_k0 + i * 16) * ldb + (bt_n4 << 2));\
        }                                                                     \
    } while (0)

#define STS_CH(buf)                                                           \
    do {                                                                      \
        char* st = sm + (buf) * STAGE_;                                       \
        _Pragma("unroll")                                                     \
        for (int i = 0; i < 2; i++) {                                         \
            uint2 hi, lo;                                                     \
            bsplit4(pa[i], hi, lo);                                           \
            int off = (a_row0 + i * 32) * PA_ + a_c4 * 8;                     \
            *(uint2*)(st + A_HI_ + off) = hi;                                 \
            *(uint2*)(st + A_LO_ + off) = lo;                                 \
        }                                                                     \
        _Pragma("unroll")                                                     \
        for (int i = 0; i < 2; i++) {                                         \
            uint2 hi, lo;                                                     \
            bsplit4(pb[i], hi, lo);                                           \
            int off = TRANSB ? ((bt_k0 + i * 16) * PB_T + bt_n4 * 8)          \
                             : ((a_row0 + i * 32) * PA_ + a_c4 * 8);          \
            *(uint2*)(st + B_HI_ + off) = hi;                                 \
            *(uint2*)(st + B_LO_ + off) = lo;                                 \
        }                                                                     \
    } while (0)

    // prologue: fill stage 0, prefetch chunk 1
    LDG_CH(0);
    STS_CH(0);
    if (nch > 1) LDG_CH(32);
    __syncthreads();

    for (int ch = 0; ch < nch; ch++) {
        const int cur = ch & 1;
        if (ch + 1 < nch) {
            STS_CH(1 - cur);
            if (ch + 2 < nch) LDG_CH((ch + 2) << 5);
        }
        // ---- compute from stage `cur`: 2 k16-steps, 3 MMAs each ----
        const uint32_t sb = smb + cur * STAGE_;
#pragma unroll
        for (int s = 0; s < 2; s++) {
            uint32_t ah[2][4], al[2][4], bh[2][2], bl[2][2];
#pragma unroll
            for (int mi = 0; mi < 2; mi++) {
                LDMX4(ah[mi], sb + A_HI_ + aoff[mi][s]);
                LDMX4(al[mi], sb + A_LO_ + aoff[mi][s]);
            }
#pragma unroll
            for (int nj = 0; nj < 2; nj++) {
                if (TRANSB) {
                    LDMX2T(bh[nj], sb + B_HI_ + boff[nj][s]);
                    LDMX2T(bl[nj], sb + B_LO_ + boff[nj][s]);
                } else {
                    LDMX2(bh[nj], sb + B_HI_ + boff[nj][s]);
                    LDMX2(bl[nj], sb + B_LO_ + boff[nj][s]);
                }
            }
#pragma unroll
            for (int mi = 0; mi < 2; mi++)
#pragma unroll
                for (int nj = 0; nj < 2; nj++) {
                    MMAB(acc[mi][nj], ah[mi], bh[nj]);
                    MMAB(acc[mi][nj], ah[mi], bl[nj]);
                    MMAB(acc[mi][nj], al[mi], bh[nj]);
                }
        }
        __syncthreads();
    }
#undef LDG_CH
#undef STS_CH

    // ---- epilogue: direct fragment stores ----
    const float* bias_b = BIAS ? (bias + (long)bz * sBiasz) : (const float*)0;
#pragma unroll
    for (int mi = 0; mi < 2; mi++)
#pragma unroll
        for (int nj = 0; nj < 2; nj++) {
            int r = m0 + wm * 32 + mi * 16 + (lane >> 2);
            int c = n0 + wn * 16 + nj * 8 + ((lane & 3) << 1);
            float2 v0 = make_float2(acc[mi][nj][0], acc[mi][nj][1]);
            float2 v1 = make_float2(acc[mi][nj][2], acc[mi][nj][3]);
            if (BIAS) {
                float b0 = bias_b[c] * bscale, b1 = bias_b[c + 1] * bscale;
                v0.x += b0; v0.y += b1; v1.x += b0; v1.y += b1;
            }
            *(float2*)&Cb[(long)r * ldc + c] = v0;
            *(float2*)&Cb[(long)(r + 8) * ldc + c] = v1;
        }
}

// ---------------- RoPE (paired: thread d handles d and d+256) -------------
__global__ __launch_bounds__(256) void rope_kernel(const float* __restrict__ kv_c) {
    const int l = blockIdx.x;
    const int b = blockIdx.y;
    const int d = threadIdx.x;  // 0..255
    const long base = ((long)b * L_ + l) * DC_;
    float x0 = kv_c[base + d];
    float x1 = kv_c[base + d + 256];
    float ex0 = (float)(d & ~1) * (1.0f / (float)DC_);
    float inv0 = exp2f(-13.287712379549449f * ex0);
    float s0, c0;
    sincosf((float)l * inv0, &s0, &c0);
    float ex1 = (float)((d + 256) & ~1) * (1.0f / (float)DC_);
    float inv1 = exp2f(-13.287712379549449f * ex1);
    float s1, c1;
    sincosf((float)l * inv1, &s1, &c1);
    g_kv[base + d] = x0 * c0 - x1 * s0;
    g_kv[base + d + 256] = x1 * c1 + x0 * s1;
}

// ---------------- kvsum[b,d] = sum_l kv[b,l,d] ----------------------------
__global__ __launch_bounds__(128) void kvsum_kernel() {
    const int b = blockIdx.x;
    const int d = blockIdx.y * 128 + threadIdx.x;
    const float* p = g_kv + (long)b * L_ * DC_ + d;
    float s = 0.f;
#pragma unroll 8
    for (int l = 0; l < L_; l++) s += p[(long)l * DC_];
    g_kvsum[b * DC_ + d] = s;
}

// ---------------- scores[b,h,d] = kvsum[b,d] * sum_r qr[b,h,r]*Wkr[h,d,r] -
__global__ __launch_bounds__(256) void scores_kernel(const float* __restrict__ Wkr) {
    const int h = blockIdx.x;
    __shared__ __align__(16) float qs[B_][R_ + 4];
    __shared__ __align__(16) float ws[64][R_ + 4];
    const int tid = threadIdx.x;
    const int tcol = tid % 16;
    const int trow = tid / 16;

#pragma unroll
    for (int i = 0; i < 16; i++) {
        int idx = tid + i * 256;
        int b = idx >> 6, r = idx & 63;
        qs[b][r] = g_qr[((long)b * H_ + h) * R_ + r];
    }

    for (int d0 = 0; d0 < DC_; d0 += 64) {
        __syncthreads();
#pragma unroll
        for (int i = 0; i < 16; i++) {
            int idx = tid + i * 256;
            int dd = idx >> 6, r = idx & 63;
            ws[dd][r] = Wkr[((long)h * DC_ + d0 + dd) * R_ + r];
        }
        __syncthreads();
        float acc[4][4];
#pragma unroll
        for (int i = 0; i < 4; i++)
#pragma unroll
            for (int j = 0; j < 4; j++) acc[i][j] = 0.f;
#pragma unroll 8
        for (int r = 0; r < R_; r++) {
            float a[4], bv[4];
#pragma unroll
            for (int i = 0; i < 4; i++) a[i] = qs[trow * 4 + i][r];
#pragma unroll
            for (int j = 0; j < 4; j++) bv[j] = ws[tcol * 4 + j][r];
#pragma unroll
            for (int i = 0; i < 4; i++)
#pragma unroll
                for (int j = 0; j < 4; j++) acc[i][j] += a[i] * bv[j];
        }
#pragma unroll
        for (int i = 0; i < 4; i++) {
            int b = trow * 4 + i;
#pragma unroll
            for (int j = 0; j < 4; j++) {
                int d = d0 + tcol * 4 + j;
                g_scores[((long)b * H_ + h) * DC_ + d] = acc[i][j] * g_kvsum[b * DC_ + d];
            }
        }
    }
}

// ---------------- softmax, then subtract uniform mode 1/512 ---------------
__global__ __launch_bounds__(128) void softmax_kernel() {
    const int bh = blockIdx.x;
    float* p = g_scores + (long)bh * DC_;
    const int tid = threadIdx.x;
    __shared__ float red[128];
    float v[4];
    float mx = -1e30f;
#pragma unroll
    for (int i = 0; i < 4; i++) {
        v[i] = p[tid + i * 128];
        mx = fmaxf(mx, v[i]);
    }
    red[tid] = mx;
    __syncthreads();
    for (int s = 64; s > 0; s >>= 1) {
        if (tid < s) red[tid] = fmaxf(red[tid], red[tid + s]);
        __syncthreads();
    }
    mx = red[0];
    __syncthreads();
    float sum = 0.f;
#pragma unroll
    for (int i = 0; i < 4; i++) {
        v[i] = expf(v[i] - mx);
        sum += v[i];
    }
    red[tid] = sum;
    __syncthreads();
    for (int s = 64; s > 0; s >>= 1) {
        if (tid < s) red[tid] += red[tid + s];
        __syncthreads();
    }
    float invs = 1.0f / red[0];
#pragma unroll
    for (int i = 0; i < 4; i++)
        p[tid + i * 128] = v[i] * invs - (1.0f / 512.0f);
}

// ---------------- split-K reduce into d_out -------------------------------
__global__ __launch_bounds__(256) void reduce_kernel(float* __restrict__ out) {
    const int i = blockIdx.x * 256 + threadIdx.x;
    float s = 0.f;
#pragma unroll
    for (int z = 0; z < SPLITS_; z++) s += g_part[(long)z * B_ * DQ_ + i];
    out[i] = s;
}

// ---------------- launch --------------------------------------------------
extern "C" void kernel_launch(void* const* d_in, const int* in_sizes, int n_in,
                              void* d_out, int out_size) {
    const float* hidden_q   = (const float*)d_in[0];
    const float* kv_c       = (const float*)d_in[1];
    const float* q_proj_w   = (const float*)d_in[2];
    const float* w_kc_q     = (const float*)d_in[3];
    const float* w_kc_kv    = (const float*)d_in[4];
    const float* W_qr       = (const float*)d_in[5];
    const float* W_kr       = (const float*)d_in[6];
    const float* out_proj_w = (const float*)d_in[7];
    float* out = (float*)d_out;

    float *qhk, *Ah, *qr, *kvsum, *scores, *ctx, *ctxlat, *part, *kv;
    cudaGetSymbolAddress((void**)&qhk,    g_qhk);
    cudaGetSymbolAddress((void**)&Ah,     g_Ah);
    cudaGetSymbolAddress((void**)&qr,     g_qr);
    cudaGetSymbolAddress((void**)&kv,     g_kv);
    cudaGetSymbolAddress((void**)&kvsum,  g_kvsum);
    cudaGetSymbolAddress((void**)&scores, g_scores);
    cudaGetSymbolAddress((void**)&ctx,    g_ctx);
    cudaGetSymbolAddress((void**)&ctxlat, g_ctxlat);
    cudaGetSymbolAddress((void**)&part,   g_part);

    rope_kernel<<<dim3(L_, B_), 256>>>(kv_c);
    kvsum_kernel<<<dim3(B_, 4), 128>>>();

    // q_hk = hidden_q @ q_proj_w^T   [64 x 16384], K=2048
    mgemm<false, false><<<dim3(256, 1, 1), 256>>>(
        hidden_q, q_proj_w, qhk, (const float*)0, 0.f, 0,
        DQ_, 0, 0, 0, DQ_, DQ_, H_ * KH_);

    // A_h = w_kc_q[h] @ W_qr[h]   (B source [q,r] -> trans)  [128 x 64] x128
    mgemm<true, false><<<dim3(1, 2, H_), 256>>>(
        w_kc_q, W_qr, Ah, (const float*)0, 0.f, 0,
        DCQ_, (long)KH_ * DCQ_, (long)DCQ_ * R_, (long)KH_ * R_,
        DCQ_, R_, R_);

    // q_r = q_hk[:,h,:] @ A_h   (B source [k,r] -> trans)  [64 x 64] x128
    mgemm<true, false><<<dim3(1, 1, H_), 256>>>(
        qhk, Ah, qr, (const float*)0, 0.f, 0,
        KH_, (long)KH_, (long)KH_ * R_, (long)R_, H_ * KH_, R_, H_ * R_);

    scores_kernel<<<H_, 256>>>(W_kr);
    softmax_kernel<<<B_ * H_, 128>>>();

    // ctx = (attn - 1/512) @ kv + kvsum/512  (B source [j,d] -> trans, bias)
    mgemm<true, true><<<dim3(DC_ / 64, 2, B_), 256>>>(
        scores, kv, ctx, kvsum, 1.0f / 512.0f, (long)DC_,
        DC_, (long)H_ * DC_, (long)L_ * DC_, (long)H_ * DC_,
        DC_, DC_, DC_);

    // ctxlat = ctx[:,h,:] @ w_kc_kv[h]^T   [64 x 128] x128
    mgemm<false, false><<<dim3(KH_ / 64, 1, H_), 256>>>(
        ctx, w_kc_kv, ctxlat, (const float*)0, 0.f, 0,
        DC_, (long)DC_, (long)KH_ * DC_, (long)KH_, H_ * DC_, DC_, H_ * KH_);

    // out = ctxlat @ out_proj_w^T  (split-K x16)
    mgemm<false, false><<<dim3(DQ_ / 64, 1, SPLITS_), 256>>>(
        ctxlat, out_proj_w, part, (const float*)0, 0.f, 0,
        H_ * KH_ / SPLITS_,
        (long)(H_ * KH_ / SPLITS_), (long)(H_ * KH_ / SPLITS_), (long)B_ * DQ_,
        H_ * KH_, H_ * KH_, DQ_);
    reduce_kernel<<<B_ * DQ_ / 256, 256>>>(out);
}

// round 8
// speedup vs baseline: 2.3809x; 1.0775x over previous
#include <cuda_runtime.h>
#include <cuda_bf16.h>
#include <math.h>
#include <stdint.h>

#define B_   64
#define L_   512
#define DQ_  2048
#define H_   128
#define KH_  128
#define DC_  512
#define DCQ_ 1536
#define R_   64

// ---------------- scratch (device globals; no allocation allowed) ----------
__device__ float g_qhk[B_ * H_ * KH_];
__device__ float g_Ah[H_ * KH_ * R_];
__device__ float g_qr[B_ * H_ * R_];
__device__ float g_kv[B_ * L_ * DC_];
__device__ float g_kvp[8 * B_ * DC_];          // rope partial sums
__device__ float g_kvsum[B_ * DC_];
__device__ float g_scores[B_ * H_ * DC_];
__device__ float g_ctx[B_ * H_ * DC_];
__device__ float g_ctxlat[B_ * H_ * KH_];
__device__ float g_part[4 * 1048576];          // split-K partials (16 MB)

// ---------------- bf16 helpers ---------------------------------------------
__device__ __forceinline__ void bsplit4(float4 v, uint2& hi, uint2& lo) {
    uint32_t h01, h23, l01, l23;
    asm("cvt.rn.bf16x2.f32 %0, %1, %2;" : "=r"(h01) : "f"(v.y), "f"(v.x));
    asm("cvt.rn.bf16x2.f32 %0, %1, %2;" : "=r"(h23) : "f"(v.w), "f"(v.z));
    float r0 = v.x - __uint_as_float(h01 << 16);
    float r1 = v.y - __uint_as_float(h01 & 0xFFFF0000u);
    float r2 = v.z - __uint_as_float(h23 << 16);
    float r3 = v.w - __uint_as_float(h23 & 0xFFFF0000u);
    asm("cvt.rn.bf16x2.f32 %0, %1, %2;" : "=r"(l01) : "f"(r1), "f"(r0));
    asm("cvt.rn.bf16x2.f32 %0, %1, %2;" : "=r"(l23) : "f"(r3), "f"(r2));
    hi.x = h01; hi.y = h23; lo.x = l01; lo.y = l23;
}

#define LDMX4(r, a)                                                           \
    asm volatile("ldmatrix.sync.aligned.m8n8.x4.shared.b16 {%0,%1,%2,%3}, [%4];" \
                 : "=r"((r)[0]), "=r"((r)[1]), "=r"((r)[2]), "=r"((r)[3])     \
                 : "r"(a))
#define LDMX2(r, a)                                                           \
    asm volatile("ldmatrix.sync.aligned.m8n8.x2.shared.b16 {%0,%1}, [%2];"    \
                 : "=r"((r)[0]), "=r"((r)[1]) : "r"(a))
#define LDMX2T(r, a)                                                          \
    asm volatile("ldmatrix.sync.aligned.m8n8.x2.trans.shared.b16 {%0,%1}, [%2];" \
                 : "=r"((r)[0]), "=r"((r)[1]) : "r"(a))

#define MMAB(d, a, b)                                                         \
    asm volatile(                                                             \
        "mma.sync.aligned.m16n8k16.row.col.f32.bf16.bf16.f32 "                \
        "{%0,%1,%2,%3}, {%4,%5,%6,%7}, {%8,%9}, {%0,%1,%2,%3};"               \
        : "+f"((d)[0]), "+f"((d)[1]), "+f"((d)[2]), "+f"((d)[3])              \
        : "r"((a)[0]), "r"((a)[1]), "r"((a)[2]), "r"((a)[3]),                 \
          "r"((b)[0]), "r"((b)[1]))

// ---------------- 3xBF16 mma.sync GEMM  (BM=64, BN=64, BK=32, 256 thr) -----
// C[m,n] = sum_k A[m,k] * B[n,k].  TRANSB: B source is [K,N] row-major.
// All operands hi/lo-split bf16; per k16 step: 3 MMAs (hh + hl + lh).
// 2-stage SMEM double buffer, prefetch distance 2. BIAS: C += bias[n]*bscale.
// Split-K: blockIdx.z = batch * nspl + sp; A/B/C offset by sp strides.
#define PA_    80
#define PB_T   144
#define A_HI_  0
#define A_LO_  5120
#define B_HI_  10240
#define B_LO_  15360
#define STAGE_ 20480

template <bool TRANSB, bool BIAS>
__global__ __launch_bounds__(256)
void mgemm(const float* __restrict__ A, const float* __restrict__ Bm,
           float* __restrict__ C, const float* __restrict__ bias,
           float bscale, long sBiasz, int Kd,
           long sAz, long sBz, long sCz, int lda, int ldb, int ldc,
           int nspl, long sAsp, long sBsp, long sCsp) {
    __shared__ __align__(16) char sm[2 * STAGE_];

    const int tid = threadIdx.x, lane = tid & 31, wid = tid >> 5;
    const int wm = wid >> 2, wn = wid & 3;
    const int n0 = blockIdx.x * 64, m0 = blockIdx.y * 64;
    int bz = blockIdx.z, sp = 0;
    if (nspl > 1) { sp = bz % nspl; bz /= nspl; }

    const float* Ab = A + (long)bz * sAz + (long)sp * sAsp + (long)m0 * lda;
    const float* Bb = (TRANSB ? (Bm + (long)bz * sBz + (long)sp * sBsp + n0)
                              : (Bm + (long)bz * sBz + (long)sp * sBsp +
                                 (long)n0 * ldb));
    float* Cb = C + (long)bz * sCz + (long)sp * sCsp;

    float acc[2][2][4];
#pragma unroll
    for (int mi = 0; mi < 2; mi++)
#pragma unroll
        for (int nj = 0; nj < 2; nj++)
#pragma unroll
            for (int e = 0; e < 4; e++) acc[mi][nj][e] = 0.f;

    const int a_row0 = tid >> 3, a_c4 = tid & 7;
    const int bt_k0 = tid >> 4, bt_n4 = tid & 15;

    const int lane7 = lane & 7, laneb = (lane >> 3) & 1, lanet = lane >> 4;
    uint32_t aoff[2][2], boff[2][2];
#pragma unroll
    for (int mi = 0; mi < 2; mi++)
#pragma unroll
        for (int s = 0; s < 2; s++)
            aoff[mi][s] = (uint32_t)((wm * 32 + mi * 16 + lane7 + laneb * 8) * PA_ +
                                     (s * 16 + lanet * 8) * 2);
#pragma unroll
    for (int nj = 0; nj < 2; nj++)
#pragma unroll
        for (int s = 0; s < 2; s++) {
            if (TRANSB)
                boff[nj][s] = (uint32_t)((s * 16 + laneb * 8 + lane7) * PB_T +
                                         (wn * 16 + nj * 8) * 2);
            else
                boff[nj][s] = (uint32_t)((wn * 16 + nj * 8 + lane7) * PA_ +
                                         (s * 16 + laneb * 8) * 2);
        }
    const uint32_t smb = (uint32_t)__cvta_generic_to_shared(sm);

    float4 pa[2], pb[2];
    const int nch = Kd >> 5;

#define LDG_CH(k0v)                                                           \
    do {                                                                      \
        _Pragma("unroll")                                                     \
        for (int i = 0; i < 2; i++)                                           \
            pa[i] = *(const float4*)(Ab + (long)(a_row0 + i * 32) * lda +     \
                                     (k0v) + (a_c4 << 2));                    \
        if (!TRANSB) {                                                        \
            _Pragma("unroll")                                                 \
            for (int i = 0; i < 2; i++)                                       \
                pb[i] = *(const float4*)(Bb + (long)(a_row0 + i * 32) * ldb + \
                                         (k0v) + (a_c4 << 2));                \
        } else {                                                              \
            _Pragma("unroll")                                                 \
            for (int i = 0; i < 2; i++)                                       \
                pb[i] = *(const float4*)(Bb +                                 \
                         (long)((k0v) + bt_k0 + i * 16) * ldb + (bt_n4 << 2));\
        }                                                                     \
    } while (0)

#define STS_CH(buf)                                                           \
    do {                                                                      \
        char* st = sm + (buf) * STAGE_;                                       \
        _Pragma("unroll")                                                     \
        for (int i = 0; i < 2; i++) {                                         \
            uint2 hi, lo;                                                     \
            bsplit4(pa[i], hi, lo);                                           \
            int off = (a_row0 + i * 32) * PA_ + a_c4 * 8;                     \
            *(uint2*)(st + A_HI_ + off) = hi;                                 \
            *(uint2*)(st + A_LO_ + off) = lo;                                 \
        }                                                                     \
        _Pragma("unroll")                                                     \
        for (int i = 0; i < 2; i++) {                                         \
            uint2 hi, lo;                                                     \
            bsplit4(pb[i], hi, lo);                                           \
            int off = TRANSB ? ((bt_k0 + i * 16) * PB_T + bt_n4 * 8)          \
                             : ((a_row0 + i * 32) * PA_ + a_c4 * 8);          \
            *(uint2*)(st + B_HI_ + off) = hi;                                 \
            *(uint2*)(st + B_LO_ + off) = lo;                                 \
        }                                                                     \
    } while (0)

    LDG_CH(0);
    STS_CH(0);
    if (nch > 1) LDG_CH(32);
    __syncthreads();

    for (int ch = 0; ch < nch; ch++) {
        const int cur = ch & 1;
        if (ch + 1 < nch) {
            STS_CH(1 - cur);
            if (ch + 2 < nch) LDG_CH((ch + 2) << 5);
        }
        const uint32_t sb = smb + cur * STAGE_;
#pragma unroll
        for (int s = 0; s < 2; s++) {
            uint32_t ah[2][4], al[2][4], bh[2][2], bl[2][2];
#pragma unroll
            for (int mi = 0; mi < 2; mi++) {
                LDMX4(ah[mi], sb + A_HI_ + aoff[mi][s]);
                LDMX4(al[mi], sb + A_LO_ + aoff[mi][s]);
            }
#pragma unroll
            for (int nj = 0; nj < 2; nj++) {
                if (TRANSB) {
                    LDMX2T(bh[nj], sb + B_HI_ + boff[nj][s]);
                    LDMX2T(bl[nj], sb + B_LO_ + boff[nj][s]);
                } else {
                    LDMX2(bh[nj], sb + B_HI_ + boff[nj][s]);
                    LDMX2(bl[nj], sb + B_LO_ + boff[nj][s]);
                }
            }
#pragma unroll
            for (int mi = 0; mi < 2; mi++)
#pragma unroll
                for (int nj = 0; nj < 2; nj++) {
                    MMAB(acc[mi][nj], ah[mi], bh[nj]);
                    MMAB(acc[mi][nj], ah[mi], bl[nj]);
                    MMAB(acc[mi][nj], al[mi], bh[nj]);
                }
        }
        __syncthreads();
    }
#undef LDG_CH
#undef STS_CH

    const float* bias_b = BIAS ? (bias + (long)bz * sBiasz) : (const float*)0;
#pragma unroll
    for (int mi = 0; mi < 2; mi++)
#pragma unroll
        for (int nj = 0; nj < 2; nj++) {
            int r = m0 + wm * 32 + mi * 16 + (lane >> 2);
            int c = n0 + wn * 16 + nj * 8 + ((lane & 3) << 1);
            float2 v0 = make_float2(acc[mi][nj][0], acc[mi][nj][1]);
            float2 v1 = make_float2(acc[mi][nj][2], acc[mi][nj][3]);
            if (BIAS) {
                float b0 = bias_b[c] * bscale, b1 = bias_b[c + 1] * bscale;
                v0.x += b0; v0.y += b1; v1.x += b0; v1.y += b1;
            }
            *(float2*)&Cb[(long)r * ldc + c] = v0;
            *(float2*)&Cb[(long)(r + 8) * ldc + c] = v1;
        }
}

// ---------------- fused RoPE + partial kvsum ------------------------------
// grid (B, 8); block 256; thread handles d and d+256 over a 64-long l slab.
__global__ __launch_bounds__(256) void rope_kernel(const float* __restrict__ kv_c) {
    const int b = blockIdx.x, lb = blockIdx.y;
    const int d = threadIdx.x;
    float ex0 = (float)(d & ~1) * (1.0f / (float)DC_);
    float inv0 = exp2f(-13.287712379549449f * ex0);
    float ex1 = (float)((d + 256) & ~1) * (1.0f / (float)DC_);
    float inv1 = exp2f(-13.287712379549449f * ex1);
    float s0 = 0.f, s1 = 0.f;
#pragma unroll 4
    for (int l = lb * 64; l < lb * 64 + 64; l++) {
        const long base = ((long)b * L_ + l) * DC_;
        float x0 = kv_c[base + d];
        float x1 = kv_c[base + d + 256];
        float sn0, c0, sn1, c1;
        sincosf((float)l * inv0, &sn0, &c0);
        sincosf((float)l * inv1, &sn1, &c1);
        float v0 = x0 * c0 - x1 * sn0;
        float v1 = x1 * c1 + x0 * sn1;
        g_kv[base + d] = v0;
        g_kv[base + d + 256] = v1;
        s0 += v0;
        s1 += v1;
    }
    g_kvp[(lb * B_ + b) * DC_ + d] = s0;
    g_kvp[(lb * B_ + b) * DC_ + d + 256] = s1;
}

__global__ __launch_bounds__(256) void kvred_kernel() {
    const int i = blockIdx.x * 256 + threadIdx.x;  // over B*DC
    float s = 0.f;
#pragma unroll
    for (int lb = 0; lb < 8; lb++) s += g_kvp[lb * (B_ * DC_) + i];
    g_kvsum[i] = s;
}

// ---------------- scores[b,h,d] = kvsum[b,d] * sum_r qr[b,h,r]*Wkr[h,d,r] -
__global__ __launch_bounds__(256) void scores_kernel(const float* __restrict__ Wkr) {
    const int h = blockIdx.x;
    __shared__ __align__(16) float qs[B_][R_ + 4];
    __shared__ __align__(16) float ws[64][R_ + 4];
    const int tid = threadIdx.x;
    const int tcol = tid % 16;
    const int trow = tid / 16;

#pragma unroll
    for (int i = 0; i < 16; i++) {
        int idx = tid + i * 256;
        int b = idx >> 6, r = idx & 63;
        qs[b][r] = g_qr[((long)b * H_ + h) * R_ + r];
    }

    for (int d0 = 0; d0 < DC_; d0 += 64) {
        __syncthreads();
#pragma unroll
        for (int i = 0; i < 16; i++) {
            int idx = tid + i * 256;
            int dd = idx >> 6, r = idx & 63;
            ws[dd][r] = Wkr[((long)h * DC_ + d0 + dd) * R_ + r];
        }
        __syncthreads();
        float acc[4][4];
#pragma unroll
        for (int i = 0; i < 4; i++)
#pragma unroll
            for (int j = 0; j < 4; j++) acc[i][j] = 0.f;
#pragma unroll 8
        for (int r = 0; r < R_; r++) {
            float a[4], bv[4];
#pragma unroll
            for (int i = 0; i < 4; i++) a[i] = qs[trow * 4 + i][r];
#pragma unroll
            for (int j = 0; j < 4; j++) bv[j] = ws[tcol * 4 + j][r];
#pragma unroll
            for (int i = 0; i < 4; i++)
#pragma unroll
                for (int j = 0; j < 4; j++) acc[i][j] += a[i] * bv[j];
        }
#pragma unroll
        for (int i = 0; i < 4; i++) {
            int b = trow * 4 + i;
#pragma unroll
            for (int j = 0; j < 4; j++) {
                int d = d0 + tcol * 4 + j;
                g_scores[((long)b * H_ + h) * DC_ + d] = acc[i][j] * g_kvsum[b * DC_ + d];
            }
        }
    }
}

// ---------------- softmax, then subtract uniform mode 1/512 ---------------
__global__ __launch_bounds__(128) void softmax_kernel() {
    const int bh = blockIdx.x;
    float* p = g_scores + (long)bh * DC_;
    const int tid = threadIdx.x;
    __shared__ float red[128];
    float v[4];
    float mx = -1e30f;
#pragma unroll
    for (int i = 0; i < 4; i++) {
        v[i] = p[tid + i * 128];
        mx = fmaxf(mx, v[i]);
    }
    red[tid] = mx;
    __syncthreads();
    for (int s = 64; s > 0; s >>= 1) {
        if (tid < s) red[tid] = fmaxf(red[tid], red[tid + s]);
        __syncthreads();
    }
    mx = red[0];
    __syncthreads();
    float sum = 0.f;
#pragma unroll
    for (int i = 0; i < 4; i++) {
        v[i] = expf(v[i] - mx);
        sum += v[i];
    }
    red[tid] = sum;
    __syncthreads();
    for (int s = 64; s > 0; s >>= 1) {
        if (tid < s) red[tid] += red[tid + s];
        __syncthreads();
    }
    float invs = 1.0f / red[0];
#pragma unroll
    for (int i = 0; i < 4; i++)
        p[tid + i * 128] = v[i] * invs - (1.0f / 512.0f);
}

// ---------------- generic split-K reduce ----------------------------------
__global__ __launch_bounds__(256) void reduceN_kernel(float* __restrict__ dst,
                                                      const float* __restrict__ src,
                                                      int parts, long stride) {
    const long i = (long)blockIdx.x * 256 + threadIdx.x;
    float s = 0.f;
    for (int p = 0; p < parts; p++) s += src[(long)p * stride + i];
    dst[i] = s;
}

// ---------------- launch --------------------------------------------------
extern "C" void kernel_launch(void* const* d_in, const int* in_sizes, int n_in,
                              void* d_out, int out_size) {
    const float* hidden_q   = (const float*)d_in[0];
    const float* kv_c       = (const float*)d_in[1];
    const float* q_proj_w   = (const float*)d_in[2];
    const float* w_kc_q     = (const float*)d_in[3];
    const float* w_kc_kv    = (const float*)d_in[4];
    const float* W_qr       = (const float*)d_in[5];
    const float* W_kr       = (const float*)d_in[6];
    const float* out_proj_w = (const float*)d_in[7];
    float* out = (float*)d_out;

    float *qhk, *Ah, *qr, *kvsum, *scores, *ctx, *ctxlat, *part, *kv;
    cudaGetSymbolAddress((void**)&qhk,    g_qhk);
    cudaGetSymbolAddress((void**)&Ah,     g_Ah);
    cudaGetSymbolAddress((void**)&qr,     g_qr);
    cudaGetSymbolAddress((void**)&kv,     g_kv);
    cudaGetSymbolAddress((void**)&kvsum,  g_kvsum);
    cudaGetSymbolAddress((void**)&scores, g_scores);
    cudaGetSymbolAddress((void**)&ctx,    g_ctx);
    cudaGetSymbolAddress((void**)&ctxlat, g_ctxlat);
    cudaGetSymbolAddress((void**)&part,   g_part);

    // RoPE + kvsum partials + tiny reduce
    rope_kernel<<<dim3(B_, 8), 256>>>(kv_c);
    kvred_kernel<<<(B_ * DC_) / 256, 256>>>();

    // q_hk = hidden_q @ q_proj_w^T   [64 x 16384], K=2048, split-K x2
    mgemm<false, false><<<dim3(256, 1, 2), 256>>>(
        hidden_q, q_proj_w, part, (const float*)0, 0.f, 0,
        1024, 0, 0, 0, DQ_, DQ_, H_ * KH_,
        2, 1024L, 1024L, (long)B_ * H_ * KH_);
    reduceN_kernel<<<(B_ * H_ * KH_) / 256, 256>>>(qhk, part, 2, (long)B_ * H_ * KH_);

    // A_h = w_kc_q[h] @ W_qr[h]   (B [q,r] -> trans)  K=1536, split-K x4
    mgemm<true, false><<<dim3(1, 2, H_ * 4), 256>>>(
        w_kc_q, W_qr, part, (const float*)0, 0.f, 0,
        384, (long)KH_ * DCQ_, (long)DCQ_ * R_, (long)KH_ * R_,
        DCQ_, R_, R_,
        4, 384L, 384L * R_, (long)H_ * KH_ * R_);
    reduceN_kernel<<<(H_ * KH_ * R_) / 256, 256>>>(Ah, part, 4, (long)H_ * KH_ * R_);

    // q_r = q_hk[:,h,:] @ A_h   (B [k,r] -> trans)  [64 x 64] x128
    mgemm<true, false><<<dim3(1, 1, H_), 256>>>(
        qhk, Ah, qr, (const float*)0, 0.f, 0,
        KH_, (long)KH_, (long)KH_ * R_, (long)R_, H_ * KH_, R_, H_ * R_,
        1, 0, 0, 0);

    scores_kernel<<<H_, 256>>>(W_kr);
    softmax_kernel<<<B_ * H_, 128>>>();

    // ctx = (attn - 1/512) @ kv + kvsum/512  (B [j,d] -> trans, bias)
    mgemm<true, true><<<dim3(DC_ / 64, 2, B_), 256>>>(
        scores, kv, ctx, kvsum, 1.0f / 512.0f, (long)DC_,
        DC_, (long)H_ * DC_, (long)L_ * DC_, (long)H_ * DC_,
        DC_, DC_, DC_,
        1, 0, 0, 0);

    // ctxlat = ctx[:,h,:] @ w_kc_kv[h]^T   [64 x 128] x128
    mgemm<false, false><<<dim3(KH_ / 64, 1, H_), 256>>>(
        ctx, w_kc_kv, ctxlat, (const float*)0, 0.f, 0,
        DC_, (long)DC_, (long)KH_ * DC_, (long)KH_, H_ * DC_, DC_, H_ * KH_,
        1, 0, 0, 0);

    // out = ctxlat @ out_proj_w^T  K=16384, split-K x16
    mgemm<false, false><<<dim3(DQ_ / 64, 1, 16), 256>>>(
        ctxlat, out_proj_w, part, (const float*)0, 0.f, 0,
        1024, 0, 0, 0, H_ * KH_, H_ * KH_, DQ_,
        16, 1024L, 1024L, (long)B_ * DQ_);
    reduceN_kernel<<<(B_ * DQ_) / 256, 256>>>(out, part, 16, (long)B_ * DQ_);
}

// round 10
// speedup vs baseline: 2.3989x; 1.0076x over previous
#include <cuda_runtime.h>
#include <cuda_bf16.h>
#include <math.h>
#include <stdint.h>

#define B_   64
#define L_   512
#define DQ_  2048
#define H_   128
#define KH_  128
#define DC_  512
#define DCQ_ 1536
#define R_   64

// ---------------- scratch (device globals; no allocation allowed) ----------
__device__ float g_qhk[B_ * H_ * KH_];
__device__ float g_Ah[H_ * KH_ * R_];
__device__ float g_qr[B_ * H_ * R_];
__device__ float g_kv[B_ * L_ * DC_];
__device__ float g_kvp[8 * B_ * DC_];
__device__ float g_kvsum[B_ * DC_];
__device__ float g_scores[B_ * H_ * DC_];
__device__ float g_ctx[B_ * H_ * DC_];
__device__ float g_ctxlat[B_ * H_ * KH_];
__device__ float g_part[4 * 1048576];

// ---------------- bf16 helpers ---------------------------------------------
__device__ __forceinline__ void bsplit4(float4 v, uint2& hi, uint2& lo) {
    uint32_t h01, h23, l01, l23;
    asm("cvt.rn.bf16x2.f32 %0, %1, %2;" : "=r"(h01) : "f"(v.y), "f"(v.x));
    asm("cvt.rn.bf16x2.f32 %0, %1, %2;" : "=r"(h23) : "f"(v.w), "f"(v.z));
    float r0 = v.x - __uint_as_float(h01 << 16);
    float r1 = v.y - __uint_as_float(h01 & 0xFFFF0000u);
    float r2 = v.z - __uint_as_float(h23 << 16);
    float r3 = v.w - __uint_as_float(h23 & 0xFFFF0000u);
    asm("cvt.rn.bf16x2.f32 %0, %1, %2;" : "=r"(l01) : "f"(r1), "f"(r0));
    asm("cvt.rn.bf16x2.f32 %0, %1, %2;" : "=r"(l23) : "f"(r3), "f"(r2));
    hi.x = h01; hi.y = h23; lo.x = l01; lo.y = l23;
}

#define LDMX4(r, a)                                                           \
    asm volatile("ldmatrix.sync.aligned.m8n8.x4.shared.b16 {%0,%1,%2,%3}, [%4];" \
                 : "=r"((r)[0]), "=r"((r)[1]), "=r"((r)[2]), "=r"((r)[3])     \
                 : "r"(a))
#define LDMX2(r, a)                                                           \
    asm volatile("ldmatrix.sync.aligned.m8n8.x2.shared.b16 {%0,%1}, [%2];"    \
                 : "=r"((r)[0]), "=r"((r)[1]) : "r"(a))
#define LDMX2T(r, a)                                                          \
    asm volatile("ldmatrix.sync.aligned.m8n8.x2.trans.shared.b16 {%0,%1}, [%2];" \
                 : "=r"((r)[0]), "=r"((r)[1]) : "r"(a))

#define MMAB(d, a, b)                                                         \
    asm volatile(                                                             \
        "mma.sync.aligned.m16n8k16.row.col.f32.bf16.bf16.f32 "                \
        "{%0,%1,%2,%3}, {%4,%5,%6,%7}, {%8,%9}, {%0,%1,%2,%3};"               \
        : "+f"((d)[0]), "+f"((d)[1]), "+f"((d)[2]), "+f"((d)[3])              \
        : "r"((a)[0]), "r"((a)[1]), "r"((a)[2]), "r"((a)[3]),                 \
          "r"((b)[0]), "r"((b)[1]))

// ---------------- 3xBF16 mma.sync GEMM  (BM=32*MI, BN=32*NJ, BK=32) --------
// C[m,n] = sum_k A[m,k] * B[n,k].  TRANSB: B source is [K,N] row-major.
// Hi/lo-split bf16; per k16 step: 3 MMAs (hh + hl + lh).
// 2-stage SMEM double buffer (dynamic), prefetch distance 2.
// Split-K: blockIdx.z = batch * nspl + sp. BIAS: C += bias[n]*bscale.
template <int MI, int NJ, bool TRANSB, bool BIAS>
__global__ __launch_bounds__(256)
void mgemm(const float* __restrict__ A, const float* __restrict__ Bm,
           float* __restrict__ C, const float* __restrict__ bias,
           float bscale, long sBiasz, int Kd,
           long sAz, long sBz, long sCz, int lda, int ldb, int ldc,
           int nspl, long sAsp, long sBsp, long sCsp) {
    constexpr int BM = 32 * MI, BN = 32 * NJ;
    constexpr int PA = 80;                    // [row][32k] bf16, +16B skew
    constexpr int PBT = BN * 2 + 16;          // [32k][BN] bf16, +16B skew
    constexpr int ASZ = BM * PA;
    constexpr int BSZ = TRANSB ? 32 * PBT : BN * PA;
    constexpr int A_HI = 0, A_LO = ASZ, B_HI = 2 * ASZ, B_LO = 2 * ASZ + BSZ;
    constexpr int STAGE = 2 * ASZ + 2 * BSZ;
    constexpr int N4 = BN / 4;                // float4 groups along n (TRANSB)
    constexpr int KSTEP_T = 256 / N4;         // k rows per staging pass

    extern __shared__ __align__(16) char sm[];

    const int tid = threadIdx.x, lane = tid & 31, wid = tid >> 5;
    const int wm = wid >> 2, wn = wid & 3;
    const int n0 = blockIdx.x * BN, m0 = blockIdx.y * BM;
    int bz = blockIdx.z, sp = 0;
    if (nspl > 1) { sp = bz % nspl; bz /= nspl; }

    const float* Ab = A + (long)bz * sAz + (long)sp * sAsp + (long)m0 * lda;
    const float* Bb = (TRANSB ? (Bm + (long)bz * sBz + (long)sp * sBsp + n0)
                              : (Bm + (long)bz * sBz + (long)sp * sBsp +
                                 (long)n0 * ldb));
    float* Cb = C + (long)bz * sCz + (long)sp * sCsp;

    float acc[MI][NJ][4];
#pragma unroll
    for (int mi = 0; mi < MI; mi++)
#pragma unroll
        for (int nj = 0; nj < NJ; nj++)
#pragma unroll
            for (int e = 0; e < 4; e++) acc[mi][nj][e] = 0.f;

    const int a_row0 = tid >> 3, a_c4 = tid & 7;
    const int bt_n4 = tid & (N4 - 1), bt_k0 = tid / N4;

    const int lane7 = lane & 7, laneb = (lane >> 3) & 1, lanet = lane >> 4;
    uint32_t aoff[MI][2], boff[NJ][2];
#pragma unroll
    for (int mi = 0; mi < MI; mi++)
#pragma unroll
        for (int s = 0; s < 2; s++)
            aoff[mi][s] = (uint32_t)((wm * (16 * MI) + mi * 16 + lane7 + laneb * 8) * PA +
                                     (s * 16 + lanet * 8) * 2);
#pragma unroll
    for (int nj = 0; nj < NJ; nj++)
#pragma unroll
        for (int s = 0; s < 2; s++) {
            if (TRANSB)
                boff[nj][s] = (uint32_t)((s * 16 + laneb * 8 + lane7) * PBT +
                                         (wn * (8 * NJ) + nj * 8) * 2);
            else
                boff[nj][s] = (uint32_t)((wn * (8 * NJ) + nj * 8 + lane7) * PA +
                                         (s * 16 + laneb * 8) * 2);
        }
    const uint32_t smb = (uint32_t)__cvta_generic_to_shared(sm);

    float4 pa[MI], pb[NJ];
    const int nch = Kd >> 5;

#define LDG_CH(k0v)                                                           \
    do {                                                                      \
        _Pragma("unroll")                                                     \
        for (int i = 0; i < MI; i++)                                          \
            pa[i] = *(const float4*)(Ab + (long)(a_row0 + i * 32) * lda +     \
                                     (k0v) + (a_c4 << 2));                    \
        if (!TRANSB) {                                                        \
            _Pragma("unroll")                                                 \
            for (int i = 0; i < NJ; i++)                                      \
                pb[i] = *(const float4*)(Bb + (long)(a_row0 + i * 32) * ldb + \
                                         (k0v) + (a_c4 << 2));                \
        } else {                                                              \
            _Pragma("unroll")                                                 \
            for (int i = 0; i < NJ; i++)                                      \
                pb[i] = *(const float4*)(Bb +                                 \
                         (long)((k0v) + bt_k0 + i * KSTEP_T) * ldb +          \
                         (bt_n4 << 2));                                       \
        }                                                                     \
    } while (0)

#define STS_CH(buf)                                                           \
    do {                                                                      \
        char* st = sm + (buf) * STAGE;                                        \
        _Pragma("unroll")                                                     \
        for (int i = 0; i < MI; i++) {                                        \
            uint2 hi, lo;                                                     \
            bsplit4(pa[i], hi, lo);                                           \
            int off = (a_row0 + i * 32) * PA + a_c4 * 8;                      \
            *(uint2*)(st + A_HI + off) = hi;                                  \
            *(uint2*)(st + A_LO + off) = lo;                                  \
        }                                                                     \
        _Pragma("unroll")                                                     \
        for (int i = 0; i < NJ; i++) {                                        \
            uint2 hi, lo;                                                     \
            bsplit4(pb[i], hi, lo);                                           \
            int off = TRANSB ? ((bt_k0 + i * KSTEP_T) * PBT + bt_n4 * 8)      \
                             : ((a_row0 + i * 32) * PA + a_c4 * 8);           \
            *(uint2*)(st + B_HI + off) = hi;                                  \
            *(uint2*)(st + B_LO + off) = lo;                                  \
        }                                                                     \
    } while (0)

    LDG_CH(0);
    STS_CH(0);
    if (nch > 1) LDG_CH(32);
    __syncthreads();

    for (int ch = 0; ch < nch; ch++) {
        const int cur = ch & 1;
        if (ch + 1 < nch) {
            STS_CH(1 - cur);
            if (ch + 2 < nch) LDG_CH((ch + 2) << 5);
        }
        const uint32_t sb = smb + cur * STAGE;
#pragma unroll
        for (int s = 0; s < 2; s++) {
            uint32_t ah[MI][4], al[MI][4], bh[NJ][2], bl[NJ][2];
#pragma unroll
            for (int mi = 0; mi < MI; mi++) {
                LDMX4(ah[mi], sb + A_HI + aoff[mi][s]);
                LDMX4(al[mi], sb + A_LO + aoff[mi][s]);
            }
#pragma unroll
            for (int nj = 0; nj < NJ; nj++) {
                if (TRANSB) {
                    LDMX2T(bh[nj], sb + B_HI + boff[nj][s]);
                    LDMX2T(bl[nj], sb + B_LO + boff[nj][s]);
                } else {
                    LDMX2(bh[nj], sb + B_HI + boff[nj][s]);
                    LDMX2(bl[nj], sb + B_LO + boff[nj][s]);
                }
            }
#pragma unroll
            for (int mi = 0; mi < MI; mi++)
#pragma unroll
                for (int nj = 0; nj < NJ; nj++) {
                    MMAB(acc[mi][nj], ah[mi], bh[nj]);
                    MMAB(acc[mi][nj], ah[mi], bl[nj]);
                    MMAB(acc[mi][nj], al[mi], bh[nj]);
                }
        }
        __syncthreads();
    }
#undef LDG_CH
#undef STS_CH

    const float* bias_b = BIAS ? (bias + (long)bz * sBiasz) : (const float*)0;
#pragma unroll
    for (int mi = 0; mi < MI; mi++)
#pragma unroll
        for (int nj = 0; nj < NJ; nj++) {
            int r = m0 + wm * (16 * MI) + mi * 16 + (lane >> 2);
            int c = n0 + wn * (8 * NJ) + nj * 8 + ((lane & 3) << 1);
            float2 v0 = make_float2(acc[mi][nj][0], acc[mi][nj][1]);
            float2 v1 = make_float2(acc[mi][nj][2], acc[mi][nj][3]);
            if (BIAS) {
                float b0 = bias_b[c] * bscale, b1 = bias_b[c + 1] * bscale;
                v0.x += b0; v0.y += b1; v1.x += b0; v1.y += b1;
            }
            *(float2*)&Cb[(long)r * ldc + c] = v0;
            *(float2*)&Cb[(long)(r + 8) * ldc + c] = v1;
        }
}

// host-side mirror of STAGE
static inline int stage_bytes(int MI, int NJ, bool TB) {
    int asz = 32 * MI * 80;
    int bsz = TB ? 32 * (32 * NJ * 2 + 16) : 32 * NJ * 80;
    return 2 * asz + 2 * bsz;
}

// ---------------- fused RoPE + partial kvsum ------------------------------
__global__ __launch_bounds__(256) void rope_kernel(const float* __restrict__ kv_c) {
    const int b = blockIdx.x, lb = blockIdx.y;
    const int d = threadIdx.x;
    float ex0 = (float)(d & ~1) * (1.0f / (float)DC_);
    float inv0 = exp2f(-13.287712379549449f * ex0);
    float ex1 = (float)((d + 256) & ~1) * (1.0f / (float)DC_);
    float inv1 = exp2f(-13.287712379549449f * ex1);
    float s0 = 0.f, s1 = 0.f;
#pragma unroll 4
    for (int l = lb * 64; l < lb * 64 + 64; l++) {
        const long base = ((long)b * L_ + l) * DC_;
        float x0 = kv_c[base + d];
        float x1 = kv_c[base + d + 256];
        float sn0, c0, sn1, c1;
        sincosf((float)l * inv0, &sn0, &c0);
        sincosf((float)l * inv1, &sn1, &c1);
        float v0 = x0 * c0 - x1 * sn0;
        float v1 = x1 * c1 + x0 * sn1;
        g_kv[base + d] = v0;
        g_kv[base + d + 256] = v1;
        s0 += v0;
        s1 += v1;
    }
    g_kvp[(lb * B_ + b) * DC_ + d] = s0;
    g_kvp[(lb * B_ + b) * DC_ + d + 256] = s1;
}

__global__ __launch_bounds__(256) void kvred_kernel() {
    const int i = blockIdx.x * 256 + threadIdx.x;
    float s = 0.f;
#pragma unroll
    for (int lb = 0; lb < 8; lb++) s += g_kvp[lb * (B_ * DC_) + i];
    g_kvsum[i] = s;
}

// ---------------- scores[b,h,d] = kvsum[b,d] * sum_r qr[b,h,r]*Wkr[h,d,r] -
__global__ __launch_bounds__(256) void scores_kernel(const float* __restrict__ Wkr) {
    const int h = blockIdx.x;
    __shared__ __align__(16) float qs[B_][R_ + 4];
    __shared__ __align__(16) float ws[64][R_ + 4];
    const int tid = threadIdx.x;
    const int tcol = tid % 16;
    const int trow = tid / 16;

#pragma unroll
    for (int i = 0; i < 16; i++) {
        int idx = tid + i * 256;
        int b = idx >> 6, r = idx & 63;
        qs[b][r] = g_qr[((long)b * H_ + h) * R_ + r];
    }

    for (int d0 = 0; d0 < DC_; d0 += 64) {
        __syncthreads();
#pragma unroll
        for (int i = 0; i < 16; i++) {
            int idx = tid + i * 256;
            int dd = idx >> 6, r = idx & 63;
            ws[dd][r] = Wkr[((long)h * DC_ + d0 + dd) * R_ + r];
        }
        __syncthreads();
        float acc[4][4];
#pragma unroll
        for (int i = 0; i < 4; i++)
#pragma unroll
            for (int j = 0; j < 4; j++) acc[i][j] = 0.f;
#pragma unroll 8
        for (int r = 0; r < R_; r++) {
            float a[4], bv[4];
#pragma unroll
            for (int i = 0; i < 4; i++) a[i] = qs[trow * 4 + i][r];
#pragma unroll
            for (int j = 0; j < 4; j++) bv[j] = ws[tcol * 4 + j][r];
#pragma unroll
            for (int i = 0; i < 4; i++)
#pragma unroll
                for (int j = 0; j < 4; j++) acc[i][j] += a[i] * bv[j];
        }
#pragma unroll
        for (int i = 0; i < 4; i++) {
            int b = trow * 4 + i;
#pragma unroll
            for (int j = 0; j < 4; j++) {
                int d = d0 + tcol * 4 + j;
                g_scores[((long)b * H_ + h) * DC_ + d] = acc[i][j] * g_kvsum[b * DC_ + d];
            }
        }
    }
}

// ---------------- softmax, then subtract uniform mode 1/512 ---------------
__global__ __launch_bounds__(128) void softmax_kernel() {
    const int bh = blockIdx.x;
    float* p = g_scores + (long)bh * DC_;
    const int tid = threadIdx.x;
    __shared__ float red[128];
    float v[4];
    float mx = -1e30f;
#pragma unroll
    for (int i = 0; i < 4; i++) {
        v[i] = p[tid + i * 128];
        mx = fmaxf(mx, v[i]);
    }
    red[tid] = mx;
    __syncthreads();
    for (int s = 64; s > 0; s >>= 1) {
        if (tid < s) red[tid] = fmaxf(red[tid], red[tid + s]);
        __syncthreads();
    }
    mx = red[0];
    __syncthreads();
    float sum = 0.f;
#pragma unroll
    for (int i = 0; i < 4; i++) {
        v[i] = expf(v[i] - mx);
        sum += v[i];
    }
    red[tid] = sum;
    __syncthreads();
    for (int s = 64; s > 0; s >>= 1) {
        if (tid < s) red[tid] += red[tid + s];
        __syncthreads();
    }
    float invs = 1.0f / red[0];
#pragma unroll
    for (int i = 0; i < 4; i++)
        p[tid + i * 128] = v[i] * invs - (1.0f / 512.0f);
}

// ---------------- generic split-K reduce ----------------------------------
__global__ __launch_bounds__(256) void reduceN_kernel(float* __restrict__ dst,
                                                      const float* __restrict__ src,
                                                      int parts, long stride) {
    const long i = (long)blockIdx.x * 256 + threadIdx.x;
    float s = 0.f;
    for (int p = 0; p < parts; p++) s += src[(long)p * stride + i];
    dst[i] = s;
}

// ---------------- launch --------------------------------------------------
extern "C" void kernel_launch(void* const* d_in, const int* in_sizes, int n_in,
                              void* d_out, int out_size) {
    const float* hidden_q   = (const float*)d_in[0];
    const float* kv_c       = (const float*)d_in[1];
    const float* q_proj_w   = (const float*)d_in[2];
    const float* w_kc_q     = (const float*)d_in[3];
    const float* w_kc_kv    = (const float*)d_in[4];
    const float* W_qr       = (const float*)d_in[5];
    const float* W_kr       = (const float*)d_in[6];
    const float* out_proj_w = (const float*)d_in[7];
    float* out = (float*)d_out;

    float *qhk, *Ah, *qr, *kvsum, *scores, *ctx, *ctxlat, *part, *kv;
    cudaGetSymbolAddress((void**)&qhk,    g_qhk);
    cudaGetSymbolAddress((void**)&Ah,     g_Ah);
    cudaGetSymbolAddress((void**)&qr,     g_qr);
    cudaGetSymbolAddress((void**)&kv,     g_kv);
    cudaGetSymbolAddress((void**)&kvsum,  g_kvsum);
    cudaGetSymbolAddress((void**)&scores, g_scores);
    cudaGetSymbolAddress((void**)&ctx,    g_ctx);
    cudaGetSymbolAddress((void**)&ctxlat, g_ctxlat);
    cudaGetSymbolAddress((void**)&part,   g_part);

    const int sm22n = 2 * stage_bytes(2, 2, false);  // 40960
    const int sm22t = 2 * stage_bytes(2, 2, true);   // 38912
    const int sm42t = 2 * stage_bytes(4, 2, true);   // 59392 (needs attr)
    cudaFuncSetAttribute(mgemm<4, 2, true, false>,
                         cudaFuncAttributeMaxDynamicSharedMemorySize, sm42t);
    cudaFuncSetAttribute(mgemm<4, 2, true, true>,
                         cudaFuncAttributeMaxDynamicSharedMemorySize, sm42t);

    // RoPE + kvsum partials + tiny reduce
    rope_kernel<<<dim3(B_, 8), 256>>>(kv_c);
    kvred_kernel<<<(B_ * DC_) / 256, 256>>>();

    // q_hk = hidden_q @ q_proj_w^T   [64 x 16384], K=2048, split-K x2
    mgemm<2, 2, false, false><<<dim3(256, 1, 2), 256, sm22n>>>(
        hidden_q, q_proj_w, part, (const float*)0, 0.f, 0,
        1024, 0, 0, 0, DQ_, DQ_, H_ * KH_,
        2, 1024L, 1024L, (long)B_ * H_ * KH_);
    reduceN_kernel<<<(B_ * H_ * KH_) / 256, 256>>>(qhk, part, 2, (long)B_ * H_ * KH_);

    // A_h = w_kc_q[h] @ W_qr[h]  (BM=128; B [q,r] -> trans)  K split x4
    mgemm<4, 2, true, false><<<dim3(1, 1, H_ * 4), 256, sm42t>>>(
        w_kc_q, W_qr, part, (const float*)0, 0.f, 0,
        384, (long)KH_ * DCQ_, (long)DCQ_ * R_, (long)KH_ * R_,
        DCQ_, R_, R_,
        4, 384L, 384L * R_, (long)H_ * KH_ * R_);
    reduceN_kernel<<<(H_ * KH_ * R_) / 256, 256>>>(Ah, part, 4, (long)H_ * KH_ * R_);

    // q_r = q_hk[:,h,:] @ A_h   (B [k,r] -> trans)  [64 x 64] x128
    mgemm<2, 2, true, false><<<dim3(1, 1, H_), 256, sm22t>>>(
        qhk, Ah, qr, (const float*)0, 0.f, 0,
        KH_, (long)KH_, (long)KH_ * R_, (long)R_, H_ * KH_, R_, H_ * R_,
        1, 0, 0, 0);

    scores_kernel<<<H_, 256>>>(W_kr);
    softmax_kernel<<<B_ * H_, 128>>>();

    // ctx = (attn - 1/512) @ kv + kvsum/512  (BM=128; B [j,d] -> trans, bias)
    mgemm<4, 2, true, true><<<dim3(DC_ / 64, 1, B_), 256, sm42t>>>(
        scores, kv, ctx, kvsum, 1.0f / 512.0f, (long)DC_,
        DC_, (long)H_ * DC_, (long)L_ * DC_, (long)H_ * DC_,
        DC_, DC_, DC_,
        1, 0, 0, 0);

    // ctxlat = ctx[:,h,:] @ w_kc_kv[h]^T   [64 x 128] x128
    mgemm<2, 2, false, false><<<dim3(KH_ / 64, 1, H_), 256, sm22n>>>(
        ctx, w_kc_kv, ctxlat, (const float*)0, 0.f, 0,
        DC_, (long)DC_, (long)KH_ * DC_, (long)KH_, H_ * DC_, DC_, H_ * KH_,
        1, 0, 0, 0);

    // out = ctxlat @ out_proj_w^T  K=16384, split-K x16
    mgemm<2, 2, false, false><<<dim3(DQ_ / 64, 1, 16), 256, sm22n>>>(
        ctxlat, out_proj_w, part, (const float*)0, 0.f, 0,
        1024, 0, 0, 0, H_ * KH_, H_ * KH_, DQ_,
        16, 1024L, 1024L, (long)B_ * DQ_);
    reduceN_kernel<<<(B_ * DQ_) / 256, 256>>>(out, part, 16, (long)B_ * DQ_);
}

// round 11
// speedup vs baseline: 2.4219x; 1.0096x over previous
#include <cuda_runtime.h>
#include <cuda_bf16.h>
#include <math.h>
#include <stdint.h>

#define B_   64
#define L_   512
#define DQ_  2048
#define H_   128
#define KH_  128
#define DC_  512
#define DCQ_ 1536
#define R_   64

// ---------------- scratch (device globals; no allocation allowed) ----------
__device__ float g_qhk[B_ * H_ * KH_];
__device__ float g_Ah[H_ * KH_ * R_];
__device__ float g_qr[B_ * H_ * R_];
__device__ float g_kv[B_ * L_ * DC_];
__device__ float g_kvp[8 * B_ * DC_];
__device__ float g_kvsum[B_ * DC_];
__device__ float g_scores[B_ * H_ * DC_];
__device__ float g_ctx[B_ * H_ * DC_];
__device__ float g_ctxlat[B_ * H_ * KH_];
__device__ float g_part[4 * 1048576];
__device__ float g_rsin[L_ * DC_];
__device__ float g_rcos[L_ * DC_];

// ---------------- bf16 helpers ---------------------------------------------
__device__ __forceinline__ void bsplit4(float4 v, uint2& hi, uint2& lo) {
    uint32_t h01, h23, l01, l23;
    asm("cvt.rn.bf16x2.f32 %0, %1, %2;" : "=r"(h01) : "f"(v.y), "f"(v.x));
    asm("cvt.rn.bf16x2.f32 %0, %1, %2;" : "=r"(h23) : "f"(v.w), "f"(v.z));
    float r0 = v.x - __uint_as_float(h01 << 16);
    float r1 = v.y - __uint_as_float(h01 & 0xFFFF0000u);
    float r2 = v.z - __uint_as_float(h23 << 16);
    float r3 = v.w - __uint_as_float(h23 & 0xFFFF0000u);
    asm("cvt.rn.bf16x2.f32 %0, %1, %2;" : "=r"(l01) : "f"(r1), "f"(r0));
    asm("cvt.rn.bf16x2.f32 %0, %1, %2;" : "=r"(l23) : "f"(r3), "f"(r2));
    hi.x = h01; hi.y = h23; lo.x = l01; lo.y = l23;
}

#define LDMX4(r, a)                                                           \
    asm volatile("ldmatrix.sync.aligned.m8n8.x4.shared.b16 {%0,%1,%2,%3}, [%4];" \
                 : "=r"((r)[0]), "=r"((r)[1]), "=r"((r)[2]), "=r"((r)[3])     \
                 : "r"(a))
#define LDMX2(r, a)                                                           \
    asm volatile("ldmatrix.sync.aligned.m8n8.x2.shared.b16 {%0,%1}, [%2];"    \
                 : "=r"((r)[0]), "=r"((r)[1]) : "r"(a))
#define LDMX2T(r, a)                                                          \
    asm volatile("ldmatrix.sync.aligned.m8n8.x2.trans.shared.b16 {%0,%1}, [%2];" \
                 : "=r"((r)[0]), "=r"((r)[1]) : "r"(a))

#define MMAB(d, a, b)                                                         \
    asm volatile(                                                             \
        "mma.sync.aligned.m16n8k16.row.col.f32.bf16.bf16.f32 "                \
        "{%0,%1,%2,%3}, {%4,%5,%6,%7}, {%8,%9}, {%0,%1,%2,%3};"               \
        : "+f"((d)[0]), "+f"((d)[1]), "+f"((d)[2]), "+f"((d)[3])              \
        : "r"((a)[0]), "r"((a)[1]), "r"((a)[2]), "r"((a)[3]),                 \
          "r"((b)[0]), "r"((b)[1]))

// ---------------- 3xBF16 mma.sync GEMM  (BM=32*MI, BN=32*NJ, BK=32) --------
template <int MI, int NJ, bool TRANSB, bool BIAS>
__global__ __launch_bounds__(256)
void mgemm(const float* __restrict__ A, const float* __restrict__ Bm,
           float* __restrict__ C, const float* __restrict__ bias,
           float bscale, long sBiasz, int Kd,
           long sAz, long sBz, long sCz, int lda, int ldb, int ldc,
           int nspl, long sAsp, long sBsp, long sCsp) {
    constexpr int BM = 32 * MI, BN = 32 * NJ;
    constexpr int PA = 80;
    constexpr int PBT = BN * 2 + 16;
    constexpr int ASZ = BM * PA;
    constexpr int BSZ = TRANSB ? 32 * PBT : BN * PA;
    constexpr int A_HI = 0, A_LO = ASZ, B_HI = 2 * ASZ, B_LO = 2 * ASZ + BSZ;
    constexpr int STAGE = 2 * ASZ + 2 * BSZ;
    constexpr int N4 = BN / 4;
    constexpr int KSTEP_T = 256 / N4;

    extern __shared__ __align__(16) char sm[];

    const int tid = threadIdx.x, lane = tid & 31, wid = tid >> 5;
    const int wm = wid >> 2, wn = wid & 3;
    const int n0 = blockIdx.x * BN, m0 = blockIdx.y * BM;
    int bz = blockIdx.z, sp = 0;
    if (nspl > 1) { sp = bz % nspl; bz /= nspl; }

    const float* Ab = A + (long)bz * sAz + (long)sp * sAsp + (long)m0 * lda;
    const float* Bb = (TRANSB ? (Bm + (long)bz * sBz + (long)sp * sBsp + n0)
                              : (Bm + (long)bz * sBz + (long)sp * sBsp +
                                 (long)n0 * ldb));
    float* Cb = C + (long)bz * sCz + (long)sp * sCsp;

    float acc[MI][NJ][4];
#pragma unroll
    for (int mi = 0; mi < MI; mi++)
#pragma unroll
        for (int nj = 0; nj < NJ; nj++)
#pragma unroll
            for (int e = 0; e < 4; e++) acc[mi][nj][e] = 0.f;

    const int a_row0 = tid >> 3, a_c4 = tid & 7;
    const int bt_n4 = tid & (N4 - 1), bt_k0 = tid / N4;

    const int lane7 = lane & 7, laneb = (lane >> 3) & 1, lanet = lane >> 4;
    uint32_t aoff[MI][2], boff[NJ][2];
#pragma unroll
    for (int mi = 0; mi < MI; mi++)
#pragma unroll
        for (int s = 0; s < 2; s++)
            aoff[mi][s] = (uint32_t)((wm * (16 * MI) + mi * 16 + lane7 + laneb * 8) * PA +
                                     (s * 16 + lanet * 8) * 2);
#pragma unroll
    for (int nj = 0; nj < NJ; nj++)
#pragma unroll
        for (int s = 0; s < 2; s++) {
            if (TRANSB)
                boff[nj][s] = (uint32_t)((s * 16 + laneb * 8 + lane7) * PBT +
                                         (wn * (8 * NJ) + nj * 8) * 2);
            else
                boff[nj][s] = (uint32_t)((wn * (8 * NJ) + nj * 8 + lane7) * PA +
                                         (s * 16 + laneb * 8) * 2);
        }
    const uint32_t smb = (uint32_t)__cvta_generic_to_shared(sm);

    float4 pa[MI], pb[NJ];
    const int nch = Kd >> 5;

#define LDG_CH(k0v)                                                           \
    do {                                                                      \
        _Pragma("unroll")                                                     \
        for (int i = 0; i < MI; i++)                                          \
            pa[i] = *(const float4*)(Ab + (long)(a_row0 + i * 32) * lda +     \
                                     (k0v) + (a_c4 << 2));                    \
        if (!TRANSB) {                                                        \
            _Pragma("unroll")                                                 \
            for (int i = 0; i < NJ; i++)                                      \
                pb[i] = *(const float4*)(Bb + (long)(a_row0 + i * 32) * ldb + \
                                         (k0v) + (a_c4 << 2));                \
        } else {                                                              \
            _Pragma("unroll")                                                 \
            for (int i = 0; i < NJ; i++)                                      \
                pb[i] = *(const float4*)(Bb +                                 \
                         (long)((k0v) + bt_k0 + i * KSTEP_T) * ldb +          \
                         (bt_n4 << 2));                                       \
        }                                                                     \
    } while (0)

#define STS_CH(buf)                                                           \
    do {                                                                      \
        char* st = sm + (buf) * STAGE;                                        \
        _Pragma("unroll")                                                     \
        for (int i = 0; i < MI; i++) {                                        \
            uint2 hi, lo;                                                     \
            bsplit4(pa[i], hi, lo);                                           \
            int off = (a_row0 + i * 32) * PA + a_c4 * 8;                      \
            *(uint2*)(st + A_HI + off) = hi;                                  \
            *(uint2*)(st + A_LO + off) = lo;                                  \
        }                                                                     \
        _Pragma("unroll")                                                     \
        for (int i = 0; i < NJ; i++) {                                        \
            uint2 hi, lo;                                                     \
            bsplit4(pb[i], hi, lo);                                           \
            int off = TRANSB ? ((bt_k0 + i * KSTEP_T) * PBT + bt_n4 * 8)      \
                             : ((a_row0 + i * 32) * PA + a_c4 * 8);           \
            *(uint2*)(st + B_HI + off) = hi;                                  \
            *(uint2*)(st + B_LO + off) = lo;                                  \
        }                                                                     \
    } while (0)

    LDG_CH(0);
    STS_CH(0);
    if (nch > 1) LDG_CH(32);
    __syncthreads();

    for (int ch = 0; ch < nch; ch++) {
        const int cur = ch & 1;
        if (ch + 1 < nch) {
            STS_CH(1 - cur);
            if (ch + 2 < nch) LDG_CH((ch + 2) << 5);
        }
        const uint32_t sb = smb + cur * STAGE;
#pragma unroll
        for (int s = 0; s < 2; s++) {
            uint32_t ah[MI][4], al[MI][4], bh[NJ][2], bl[NJ][2];
#pragma unroll
            for (int mi = 0; mi < MI; mi++) {
                LDMX4(ah[mi], sb + A_HI + aoff[mi][s]);
                LDMX4(al[mi], sb + A_LO + aoff[mi][s]);
            }
#pragma unroll
            for (int nj = 0; nj < NJ; nj++) {
                if (TRANSB) {
                    LDMX2T(bh[nj], sb + B_HI + boff[nj][s]);
                    LDMX2T(bl[nj], sb + B_LO + boff[nj][s]);
                } else {
                    LDMX2(bh[nj], sb + B_HI + boff[nj][s]);
                    LDMX2(bl[nj], sb + B_LO + boff[nj][s]);
                }
            }
#pragma unroll
            for (int mi = 0; mi < MI; mi++)
#pragma unroll
                for (int nj = 0; nj < NJ; nj++) {
                    MMAB(acc[mi][nj], ah[mi], bh[nj]);
                    MMAB(acc[mi][nj], ah[mi], bl[nj]);
                    MMAB(acc[mi][nj], al[mi], bh[nj]);
                }
        }
        __syncthreads();
    }
#undef LDG_CH
#undef STS_CH

    const float* bias_b = BIAS ? (bias + (long)bz * sBiasz) : (const float*)0;
#pragma unroll
    for (int mi = 0; mi < MI; mi++)
#pragma unroll
        for (int nj = 0; nj < NJ; nj++) {
            int r = m0 + wm * (16 * MI) + mi * 16 + (lane >> 2);
            int c = n0 + wn * (8 * NJ) + nj * 8 + ((lane & 3) << 1);
            float2 v0 = make_float2(acc[mi][nj][0], acc[mi][nj][1]);
            float2 v1 = make_float2(acc[mi][nj][2], acc[mi][nj][3]);
            if (BIAS) {
                float b0 = bias_b[c] * bscale, b1 = bias_b[c + 1] * bscale;
                v0.x += b0; v0.y += b1; v1.x += b0; v1.y += b1;
            }
            *(float2*)&Cb[(long)r * ldc + c] = v0;
            *(float2*)&Cb[(long)(r + 8) * ldc + c] = v1;
        }
}

static inline int stage_bytes(int MI, int NJ, bool TB) {
    int asz = 32 * MI * 80;
    int bsz = TB ? 32 * (32 * NJ * 2 + 16) : 32 * NJ * 80;
    return 2 * asz + 2 * bsz;
}

// ---------------- RoPE table: sin/cos per (l, d) once ---------------------
__global__ __launch_bounds__(512) void rope_tab_kernel() {
    const int l = blockIdx.x;
    const int d = threadIdx.x;
    float ex = (float)(d & ~1) * (1.0f / (float)DC_);
    float inv = exp2f(-13.287712379549449f * ex);  // 10000^{-ex}
    float s, c;
    sincosf((float)l * inv, &s, &c);
    g_rsin[l * DC_ + d] = s;
    g_rcos[l * DC_ + d] = c;
}

// ---------------- fused RoPE (table lookup) + partial kvsum ---------------
__global__ __launch_bounds__(256) void rope_kernel(const float* __restrict__ kv_c) {
    const int b = blockIdx.x, lb = blockIdx.y;
    const int d = threadIdx.x;
    float s0 = 0.f, s1 = 0.f;
#pragma unroll 4
    for (int l = lb * 64; l < lb * 64 + 64; l++) {
        const long base = ((long)b * L_ + l) * DC_;
        const int tbase = l * DC_ + d;
        float x0 = kv_c[base + d];
        float x1 = kv_c[base + d + 256];
        float sn0 = g_rsin[tbase],       c0 = g_rcos[tbase];
        float sn1 = g_rsin[tbase + 256], c1 = g_rcos[tbase + 256];
        float v0 = x0 * c0 - x1 * sn0;
        float v1 = x1 * c1 + x0 * sn1;
        g_kv[base + d] = v0;
        g_kv[base + d + 256] = v1;
        s0 += v0;
        s1 += v1;
    }
    g_kvp[(lb * B_ + b) * DC_ + d] = s0;
    g_kvp[(lb * B_ + b) * DC_ + d + 256] = s1;
}

__global__ __launch_bounds__(256) void kvred_kernel() {
    const int i = blockIdx.x * 256 + threadIdx.x;
    float s = 0.f;
#pragma unroll
    for (int lb = 0; lb < 8; lb++) s += g_kvp[lb * (B_ * DC_) + i];
    g_kvsum[i] = s;
}

// ---------------- scores[b,h,d] = kvsum[b,d] * sum_r qr[b,h,r]*Wkr[h,d,r] -
__global__ __launch_bounds__(256) void scores_kernel(const float* __restrict__ Wkr) {
    const int h = blockIdx.x;
    __shared__ __align__(16) float qs[B_][R_ + 4];
    __shared__ __align__(16) float ws[64][R_ + 4];
    const int tid = threadIdx.x;
    const int tcol = tid % 16;
    const int trow = tid / 16;

#pragma unroll
    for (int i = 0; i < 16; i++) {
        int idx = tid + i * 256;
        int b = idx >> 6, r = idx & 63;
        qs[b][r] = g_qr[((long)b * H_ + h) * R_ + r];
    }

    for (int d0 = 0; d0 < DC_; d0 += 64) {
        __syncthreads();
#pragma unroll
        for (int i = 0; i < 16; i++) {
            int idx = tid + i * 256;
            int dd = idx >> 6, r = idx & 63;
            ws[dd][r] = Wkr[((long)h * DC_ + d0 + dd) * R_ + r];
        }
        __syncthreads();
        float acc[4][4];
#pragma unroll
        for (int i = 0; i < 4; i++)
#pragma unroll
            for (int j = 0; j < 4; j++) acc[i][j] = 0.f;
#pragma unroll 8
        for (int r = 0; r < R_; r++) {
            float a[4], bv[4];
#pragma unroll
            for (int i = 0; i < 4; i++) a[i] = qs[trow * 4 + i][r];
#pragma unroll
            for (int j = 0; j < 4; j++) bv[j] = ws[tcol * 4 + j][r];
#pragma unroll
            for (int i = 0; i < 4; i++)
#pragma unroll
                for (int j = 0; j < 4; j++) acc[i][j] += a[i] * bv[j];
        }
#pragma unroll
        for (int i = 0; i < 4; i++) {
            int b = trow * 4 + i;
#pragma unroll
            for (int j = 0; j < 4; j++) {
                int d = d0 + tcol * 4 + j;
                g_scores[((long)b * H_ + h) * DC_ + d] = acc[i][j] * g_kvsum[b * DC_ + d];
            }
        }
    }
}

// ---------------- softmax, then subtract uniform mode 1/512 ---------------
__global__ __launch_bounds__(128) void softmax_kernel() {
    const int bh = blockIdx.x;
    float* p = g_scores + (long)bh * DC_;
    const int tid = threadIdx.x;
    __shared__ float red[128];
    float v[4];
    float mx = -1e30f;
#pragma unroll
    for (int i = 0; i < 4; i++) {
        v[i] = p[tid + i * 128];
        mx = fmaxf(mx, v[i]);
    }
    red[tid] = mx;
    __syncthreads();
    for (int s = 64; s > 0; s >>= 1) {
        if (tid < s) red[tid] = fmaxf(red[tid], red[tid + s]);
        __syncthreads();
    }
    mx = red[0];
    __syncthreads();
    float sum = 0.f;
#pragma unroll
    for (int i = 0; i < 4; i++) {
        v[i] = expf(v[i] - mx);
        sum += v[i];
    }
    red[tid] = sum;
    __syncthreads();
    for (int s = 64; s > 0; s >>= 1) {
        if (tid < s) red[tid] += red[tid + s];
        __syncthreads();
    }
    float invs = 1.0f / red[0];
#pragma unroll
    for (int i = 0; i < 4; i++)
        p[tid + i * 128] = v[i] * invs - (1.0f / 512.0f);
}

// ---------------- generic split-K reduce ----------------------------------
__global__ __launch_bounds__(256) void reduceN_kernel(float* __restrict__ dst,
                                                      const float* __restrict__ src,
                                                      int parts, long stride) {
    const long i = (long)blockIdx.x * 256 + threadIdx.x;
    float s = 0.f;
    for (int p = 0; p < parts; p++) s += src[(long)p * stride + i];
    dst[i] = s;
}

// ---------------- launch --------------------------------------------------
extern "C" void kernel_launch(void* const* d_in, const int* in_sizes, int n_in,
                              void* d_out, int out_size) {
    const float* hidden_q   = (const float*)d_in[0];
    const float* kv_c       = (const float*)d_in[1];
    const float* q_proj_w   = (const float*)d_in[2];
    const float* w_kc_q     = (const float*)d_in[3];
    const float* w_kc_kv    = (const float*)d_in[4];
    const float* W_qr       = (const float*)d_in[5];
    const float* W_kr       = (const float*)d_in[6];
    const float* out_proj_w = (const float*)d_in[7];
    float* out = (float*)d_out;

    float *qhk, *Ah, *qr, *kvsum, *scores, *ctx, *ctxlat, *part, *kv;
    cudaGetSymbolAddress((void**)&qhk,    g_qhk);
    cudaGetSymbolAddress((void**)&Ah,     g_Ah);
    cudaGetSymbolAddress((void**)&qr,     g_qr);
    cudaGetSymbolAddress((void**)&kv,     g_kv);
    cudaGetSymbolAddress((void**)&kvsum,  g_kvsum);
    cudaGetSymbolAddress((void**)&scores, g_scores);
    cudaGetSymbolAddress((void**)&ctx,    g_ctx);
    cudaGetSymbolAddress((void**)&ctxlat, g_ctxlat);
    cudaGetSymbolAddress((void**)&part,   g_part);

    const int sm22n = 2 * stage_bytes(2, 2, false);
    const int sm22t = 2 * stage_bytes(2, 2, true);
    const int sm42t = 2 * stage_bytes(4, 2, true);
    cudaFuncSetAttribute(mgemm<4, 2, true, false>,
                         cudaFuncAttributeMaxDynamicSharedMemorySize, sm42t);
    cudaFuncSetAttribute(mgemm<4, 2, true, true>,
                         cudaFuncAttributeMaxDynamicSharedMemorySize, sm42t);

    // RoPE tables (once per launch; tiny) + fused rope/kvsum + reduce
    rope_tab_kernel<<<L_, 512>>>();
    rope_kernel<<<dim3(B_, 8), 256>>>(kv_c);
    kvred_kernel<<<(B_ * DC_) / 256, 256>>>();

    // q_hk = hidden_q @ q_proj_w^T   [64 x 16384], K=2048, split-K x4
    mgemm<2, 2, false, false><<<dim3(256, 1, 4), 256, sm22n>>>(
        hidden_q, q_proj_w, part, (const float*)0, 0.f, 0,
        512, 0, 0, 0, DQ_, DQ_, H_ * KH_,
        4, 512L, 512L, (long)B_ * H_ * KH_);
    reduceN_kernel<<<(B_ * H_ * KH_) / 256, 256>>>(qhk, part, 4, (long)B_ * H_ * KH_);

    // A_h = w_kc_q[h] @ W_qr[h]  (BM=128; B [q,r] -> trans)  K split x4
    mgemm<4, 2, true, false><<<dim3(1, 1, H_ * 4), 256, sm42t>>>(
        w_kc_q, W_qr, part, (const float*)0, 0.f, 0,
        384, (long)KH_ * DCQ_, (long)DCQ_ * R_, (long)KH_ * R_,
        DCQ_, R_, R_,
        4, 384L, 384L * R_, (long)H_ * KH_ * R_);
    reduceN_kernel<<<(H_ * KH_ * R_) / 256, 256>>>(Ah, part, 4, (long)H_ * KH_ * R_);

    // q_r = q_hk[:,h,:] @ A_h   (B [k,r] -> trans)  [64 x 64] x128
    mgemm<2, 2, true, false><<<dim3(1, 1, H_), 256, sm22t>>>(
        qhk, Ah, qr, (const float*)0, 0.f, 0,
        KH_, (long)KH_, (long)KH_ * R_, (long)R_, H_ * KH_, R_, H_ * R_,
        1, 0, 0, 0);

    scores_kernel<<<H_, 256>>>(W_kr);
    softmax_kernel<<<B_ * H_, 128>>>();

    // ctx = (attn - 1/512) @ kv + kvsum/512  (BM=128; B [j,d] -> trans, bias)
    mgemm<4, 2, true, true><<<dim3(DC_ / 64, 1, B_), 256, sm42t>>>(
        scores, kv, ctx, kvsum, 1.0f / 512.0f, (long)DC_,
        DC_, (long)H_ * DC_, (long)L_ * DC_, (long)H_ * DC_,
        DC_, DC_, DC_,
        1, 0, 0, 0);

    // ctxlat = ctx[:,h,:] @ w_kc_kv[h]^T   [64 x 128] x128
    mgemm<2, 2, false, false><<<dim3(KH_ / 64, 1, H_), 256, sm22n>>>(
        ctx, w_kc_kv, ctxlat, (const float*)0, 0.f, 0,
        DC_, (long)DC_, (long)KH_ * DC_, (long)KH_, H_ * DC_, DC_, H_ * KH_,
        1, 0, 0, 0);

    // out = ctxlat @ out_proj_w^T  K=16384, split-K x16
    mgemm<2, 2, false, false><<<dim3(DQ_ / 64, 1, 16), 256, sm22n>>>(
        ctxlat, out_proj_w, part, (const float*)0, 0.f, 0,
        1024, 0, 0, 0, H_ * KH_, H_ * KH_, DQ_,
        16, 1024L, 1024L, (long)B_ * DQ_);
    reduceN_kernel<<<(B_ * DQ_) / 256, 256>>>(out, part, 16, (long)B_ * DQ_);
}